// round 2
// baseline (speedup 1.0000x reference)
#include <cuda_runtime.h>
#include <math.h>

// Problem constants
#define B_BATCH 64
#define N_SEQ   512
#define D_MOD   512
#define H_HEADS 8
#define DK_HEAD 64
#define BN_TOT  32768           // B*N rows
#define SLOT    16777216u       // BN_TOT * 512 floats

// Scratch arena (5 x 64MB slots, reused across pipeline stages)
//  slot0: Q        -> later h (post-BN1)
//  slot1: K        -> later ff1
//  slot2: V        -> later ff2
//  slot3: heads_cat (B*N, H*DK)
//  slot4: proj (attention output projection)
__device__ float g_arena[5u * SLOT];
__device__ float g_psum[256 * 512];
__device__ float g_psq[256 * 512];
__device__ float g_gamma[512];
__device__ float g_beta[512];

// ---------------------------------------------------------------------------
// Generic 64x64-tile SGEMM core. BM=BN=64, BK=16, 256 threads, 4x4 per thread.
// A: (M x K) row-major, lda.  C: row-major, ldc.
// TRANSB=false: B is (K x N) row-major, ldb.
// TRANSB=true : B is (N x K) row-major, ldb (i.e. torch Linear weight, C=A@B^T).
// ---------------------------------------------------------------------------
template<bool TRANSB, bool RELU>
__device__ __forceinline__ void gemm64(
    const float* __restrict__ A, const float* __restrict__ B,
    float* __restrict__ C, int K, int lda, int ldb, int ldc,
    const float* __restrict__ bias, int m0, int n0)
{
    __shared__ float As[16][64];   // [k][m] (A tile transposed)
    __shared__ float Bs[16][64];   // [k][n]
    const int tid = threadIdx.x;
    const int tx = tid & 15, ty = tid >> 4;

    float acc[4][4];
#pragma unroll
    for (int i = 0; i < 4; i++)
#pragma unroll
        for (int j = 0; j < 4; j++) acc[i][j] = 0.f;

    const int ar  = tid >> 2;          // 0..63 (A tile row)
    const int ac4 = (tid & 3) * 4;     // 0,4,8,12 (A tile col base)

    for (int k0 = 0; k0 < K; k0 += 16) {
        // prefetch global
        float4 av = *(const float4*)(A + (size_t)(m0 + ar) * lda + k0 + ac4);
        float4 bv;
        if (!TRANSB) {
            int kr  = tid >> 4;            // 0..15
            int nc4 = (tid & 15) * 4;      // 0..60
            bv = *(const float4*)(B + (size_t)(k0 + kr) * ldb + n0 + nc4);
        } else {
            int nr  = tid >> 2;            // 0..63
            int kc4 = (tid & 3) * 4;
            bv = *(const float4*)(B + (size_t)(n0 + nr) * ldb + k0 + kc4);
        }
        __syncthreads();   // previous compute done before overwriting tiles
        As[ac4 + 0][ar] = av.x; As[ac4 + 1][ar] = av.y;
        As[ac4 + 2][ar] = av.z; As[ac4 + 3][ar] = av.w;
        if (!TRANSB) {
            int kr  = tid >> 4;
            int nc4 = (tid & 15) * 4;
            *(float4*)&Bs[kr][nc4] = bv;
        } else {
            int nr  = tid >> 2;
            int kc4 = (tid & 3) * 4;
            Bs[kc4 + 0][nr] = bv.x; Bs[kc4 + 1][nr] = bv.y;
            Bs[kc4 + 2][nr] = bv.z; Bs[kc4 + 3][nr] = bv.w;
        }
        __syncthreads();
#pragma unroll
        for (int k = 0; k < 16; k++) {
            float4 a4 = *(const float4*)&As[k][ty * 4];
            float4 b4 = *(const float4*)&Bs[k][tx * 4];
            float a[4] = {a4.x, a4.y, a4.z, a4.w};
            float b[4] = {b4.x, b4.y, b4.z, b4.w};
#pragma unroll
            for (int i = 0; i < 4; i++)
#pragma unroll
                for (int j = 0; j < 4; j++)
                    acc[i][j] += a[i] * b[j];
        }
    }

    // epilogue
    float4 bb = make_float4(0.f, 0.f, 0.f, 0.f);
    if (bias) bb = *(const float4*)&bias[n0 + tx * 4];
#pragma unroll
    for (int i = 0; i < 4; i++) {
        float4 v = make_float4(acc[i][0] + bb.x, acc[i][1] + bb.y,
                               acc[i][2] + bb.z, acc[i][3] + bb.w);
        if (RELU) {
            v.x = fmaxf(v.x, 0.f); v.y = fmaxf(v.y, 0.f);
            v.z = fmaxf(v.z, 0.f); v.w = fmaxf(v.w, 0.f);
        }
        *(float4*)&C[(size_t)(m0 + ty * 4 + i) * ldc + n0 + tx * 4] = v;
    }
}

// ---------------------------------------------------------------------------
// QKV projection: grid (1, M/64, 24). z -> (which, head).
// C layout per which: [h][m][k]  (contiguous (512x64) block per (h,b))
// ---------------------------------------------------------------------------
__global__ __launch_bounds__(256) void k_qkv(
    const float* __restrict__ x, const float* __restrict__ Wq,
    const float* __restrict__ Wk, const float* __restrict__ Wv)
{
    int z = blockIdx.z;
    int which = z >> 3, h = z & 7;
    const float* W = (which == 0 ? Wq : (which == 1 ? Wk : Wv)) + (size_t)h * D_MOD * DK_HEAD;
    float* C = g_arena + (size_t)which * SLOT + (size_t)h * (BN_TOT * DK_HEAD);
    gemm64<false, false>(x, W, C, D_MOD, D_MOD, DK_HEAD, DK_HEAD, nullptr,
                         blockIdx.y * 64, blockIdx.x * 64);
}

// NN GEMM between arena slots / external B. aslot/cslot select arena buffers.
__global__ __launch_bounds__(256) void k_gemm_nn_slots(
    int aslot, const float* __restrict__ B, int cslot,
    int K, int lda, int ldb, int ldc, const float* __restrict__ bias)
{
    const float* A = g_arena + (size_t)aslot * SLOT;
    float* C = g_arena + (size_t)cslot * SLOT;
    gemm64<false, false>(A, B, C, K, lda, ldb, ldc, bias, blockIdx.y * 64, blockIdx.x * 64);
}

__global__ __launch_bounds__(256) void k_gemm_tn_relu_slots(
    int aslot, const float* __restrict__ B, int cslot,
    int K, int lda, int ldb, int ldc, const float* __restrict__ bias)
{
    const float* A = g_arena + (size_t)aslot * SLOT;
    float* C = g_arena + (size_t)cslot * SLOT;
    gemm64<true, true>(A, B, C, K, lda, ldb, ldc, bias, blockIdx.y * 64, blockIdx.x * 64);
}

__global__ __launch_bounds__(256) void k_gemm_tn_slots(
    int aslot, const float* __restrict__ B, int cslot,
    int K, int lda, int ldb, int ldc, const float* __restrict__ bias)
{
    const float* A = g_arena + (size_t)aslot * SLOT;
    float* C = g_arena + (size_t)cslot * SLOT;
    gemm64<true, false>(A, B, C, K, lda, ldb, ldc, bias, blockIdx.y * 64, blockIdx.x * 64);
}

// ---------------------------------------------------------------------------
// Fused flash attention per (h, b, q-tile). 256 threads, 64 queries per block.
// smem: Qst (Q^T) + KPs (K^T, reused as P) + Vs = 48KB static.
// Writes heads concatenated: heads_cat[m][h*64 + dk], m = b*512 + q.
// ---------------------------------------------------------------------------
__global__ __launch_bounds__(256) void k_attn()
{
    const int h = blockIdx.z, b = blockIdx.y, q0 = blockIdx.x * 64;
    const size_t hb = ((size_t)h * BN_TOT + (size_t)b * N_SEQ) * DK_HEAD;
    const float* Q = g_arena + 0 * (size_t)SLOT + hb;
    const float* K = g_arena + 1 * (size_t)SLOT + hb;
    const float* V = g_arena + 2 * (size_t)SLOT + hb;
    float* OUT = g_arena + 3 * (size_t)SLOT;

    __shared__ float Qst[64][64];   // [d][r]
    __shared__ float KPs[64][64];   // K^T [d][kj], reused as P [r][kj]
    __shared__ float Vs[64][64];    // [kj][d]

    const int tid = threadIdx.x;
    const int tx = tid & 15, ty = tid >> 4;
    const int lr  = tid >> 2;            // 0..63 load row
    const int lcb = (tid & 3) * 16;      // load col base (16 floats per thread/row)

    // load Q tile transposed
#pragma unroll
    for (int u = 0; u < 4; u++) {
        float4 v = *(const float4*)(Q + (size_t)(q0 + lr) * DK_HEAD + lcb + u * 4);
        Qst[lcb + u * 4 + 0][lr] = v.x; Qst[lcb + u * 4 + 1][lr] = v.y;
        Qst[lcb + u * 4 + 2][lr] = v.z; Qst[lcb + u * 4 + 3][lr] = v.w;
    }

    float m_[4], l_[4], acc[4][4];
#pragma unroll
    for (int i = 0; i < 4; i++) {
        m_[i] = -1e30f; l_[i] = 0.f;
#pragma unroll
        for (int j = 0; j < 4; j++) acc[i][j] = 0.f;
    }

    const float scale = 0.125f;   // 1/sqrt(64)

    for (int kt = 0; kt < 8; kt++) {
        __syncthreads();   // previous PV reads done
        // load K tile transposed, V tile direct
        const float* Kt = K + (size_t)kt * 64 * DK_HEAD;
        const float* Vt = V + (size_t)kt * 64 * DK_HEAD;
#pragma unroll
        for (int u = 0; u < 4; u++) {
            float4 v = *(const float4*)(Kt + (size_t)lr * DK_HEAD + lcb + u * 4);
            KPs[lcb + u * 4 + 0][lr] = v.x; KPs[lcb + u * 4 + 1][lr] = v.y;
            KPs[lcb + u * 4 + 2][lr] = v.z; KPs[lcb + u * 4 + 3][lr] = v.w;
            float4 w = *(const float4*)(Vt + (size_t)lr * DK_HEAD + lcb + u * 4);
            *(float4*)&Vs[lr][lcb + u * 4] = w;
        }
        __syncthreads();

        // S = Q @ K^T * scale  (4x4 per thread)
        float s[4][4];
#pragma unroll
        for (int i = 0; i < 4; i++)
#pragma unroll
            for (int j = 0; j < 4; j++) s[i][j] = 0.f;
#pragma unroll 8
        for (int d = 0; d < 64; d++) {
            float4 a4 = *(const float4*)&Qst[d][ty * 4];
            float4 b4 = *(const float4*)&KPs[d][tx * 4];
            float a[4] = {a4.x, a4.y, a4.z, a4.w};
            float bb[4] = {b4.x, b4.y, b4.z, b4.w};
#pragma unroll
            for (int i = 0; i < 4; i++)
#pragma unroll
                for (int j = 0; j < 4; j++)
                    s[i][j] += a[i] * bb[j];
        }

        // online softmax update
        float alpha[4];
#pragma unroll
        for (int i = 0; i < 4; i++) {
            float rm = -1e30f;
#pragma unroll
            for (int j = 0; j < 4; j++) { s[i][j] *= scale; rm = fmaxf(rm, s[i][j]); }
#pragma unroll
            for (int msk = 8; msk >= 1; msk >>= 1)
                rm = fmaxf(rm, __shfl_xor_sync(0xffffffffu, rm, msk));
            float mnew = fmaxf(m_[i], rm);
            alpha[i] = __expf(m_[i] - mnew);
            float rs = 0.f;
#pragma unroll
            for (int j = 0; j < 4; j++) { s[i][j] = __expf(s[i][j] - mnew); rs += s[i][j]; }
#pragma unroll
            for (int msk = 8; msk >= 1; msk >>= 1)
                rs += __shfl_xor_sync(0xffffffffu, rs, msk);
            l_[i] = l_[i] * alpha[i] + rs;
            m_[i] = mnew;
#pragma unroll
            for (int j = 0; j < 4; j++) acc[i][j] *= alpha[i];
        }

        __syncthreads();   // all K^T reads done, safe to overwrite with P
#pragma unroll
        for (int i = 0; i < 4; i++)
            *(float4*)&KPs[ty * 4 + i][tx * 4] =
                make_float4(s[i][0], s[i][1], s[i][2], s[i][3]);
        __syncthreads();

        // O += P @ V
#pragma unroll 8
        for (int kj = 0; kj < 64; kj++) {
            float4 b4 = *(const float4*)&Vs[kj][tx * 4];
            float bb[4] = {b4.x, b4.y, b4.z, b4.w};
#pragma unroll
            for (int i = 0; i < 4; i++) {
                float a = KPs[ty * 4 + i][kj];
#pragma unroll
                for (int j = 0; j < 4; j++)
                    acc[i][j] += a * bb[j];
            }
        }
    }

    // normalize and store to heads_cat
#pragma unroll
    for (int i = 0; i < 4; i++) {
        float inv = 1.f / l_[i];
        size_t row = (size_t)b * N_SEQ + q0 + ty * 4 + i;
        *(float4*)&OUT[row * D_MOD + h * DK_HEAD + tx * 4] =
            make_float4(acc[i][0] * inv, acc[i][1] * inv,
                        acc[i][2] * inv, acc[i][3] * inv);
    }
}

// ---------------------------------------------------------------------------
// Deterministic two-stage BatchNorm (training stats, biased variance).
// t = scale * (A [+ Bopt]); stats per column over 32768 rows.
// ---------------------------------------------------------------------------
__global__ __launch_bounds__(256) void k_bnstats(
    int aslot, int bslot, float scale)
{
    const float* A = g_arena + (size_t)aslot * SLOT;
    const float* Bopt = (bslot >= 0) ? (g_arena + (size_t)bslot * SLOT) : nullptr;
    int c = blockIdx.x * 256 + threadIdx.x;   // grid.x = 2 -> 512 cols
    int chunk = blockIdx.y;                   // 256 chunks of 128 rows
    int r0 = chunk * 128;
    float s = 0.f, q = 0.f;
    for (int r = r0; r < r0 + 128; r++) {
        float t = A[(size_t)r * 512 + c];
        if (Bopt) t += Bopt[(size_t)r * 512 + c];
        t *= scale;
        s += t; q += t * t;
    }
    g_psum[chunk * 512 + c] = s;
    g_psq[chunk * 512 + c]  = q;
}

__global__ __launch_bounds__(512) void k_bnfinal(
    const float* __restrict__ w, const float* __restrict__ bias)
{
    int c = threadIdx.x;
    float s = 0.f, q = 0.f;
    for (int i = 0; i < 256; i++) { s += g_psum[i * 512 + c]; q += g_psq[i * 512 + c]; }
    float m   = s * (1.f / 32768.f);
    float var = q * (1.f / 32768.f) - m * m;
    float inv = rsqrtf(var + 1e-5f);
    float g   = inv * w[c];
    g_gamma[c] = g;
    g_beta[c]  = bias[c] - m * g;
}

// outslot >= 0: write to arena slot; else write to ext_out.
__global__ __launch_bounds__(256) void k_bnapply(
    int aslot, int bslot, float scale, int outslot, float* __restrict__ ext_out)
{
    const float* A = g_arena + (size_t)aslot * SLOT;
    const float* Bopt = (bslot >= 0) ? (g_arena + (size_t)bslot * SLOT) : nullptr;
    float* out = (outslot >= 0) ? (g_arena + (size_t)outslot * SLOT) : ext_out;
    size_t i = ((size_t)blockIdx.x * 256 + threadIdx.x) * 4;
    int c = (int)(i & 511);
    float4 a = *(const float4*)(A + i);
    if (Bopt) {
        float4 b = *(const float4*)(Bopt + i);
        a.x += b.x; a.y += b.y; a.z += b.z; a.w += b.w;
    }
    float4 g = *(const float4*)&g_gamma[c];
    float4 bt = *(const float4*)&g_beta[c];
    float4 y;
    y.x = scale * a.x * g.x + bt.x;
    y.y = scale * a.y * g.y + bt.y;
    y.z = scale * a.z * g.z + bt.z;
    y.w = scale * a.w * g.w + bt.w;
    *(float4*)(out + i) = y;
}

// ---------------------------------------------------------------------------
// Launch pipeline (kernel launches only — fully graph-capturable)
// ---------------------------------------------------------------------------
extern "C" void kernel_launch(void* const* d_in, const int* in_sizes, int n_in,
                              void* d_out, int out_size)
{
    const float* x    = (const float*)d_in[0];
    const float* Wq   = (const float*)d_in[1];
    const float* Wk   = (const float*)d_in[2];
    const float* Wv   = (const float*)d_in[3];
    const float* Wo   = (const float*)d_in[4];
    const float* n1w  = (const float*)d_in[5];
    const float* n1b  = (const float*)d_in[6];
    const float* n2w  = (const float*)d_in[7];
    const float* n2b  = (const float*)d_in[8];
    const float* ffw1 = (const float*)d_in[9];
    const float* ffb1 = (const float*)d_in[10];
    const float* ffw2 = (const float*)d_in[11];
    const float* ffb2 = (const float*)d_in[12];

    // Arena slot map:
    //  0: Q  -> h (post-BN1)      1: K -> ff1      2: V -> ff2
    //  3: heads_cat               4: proj

    // 1. QKV projections: 24 GEMMs (3 x 8 heads), M=32768, N=64, K=512
    k_qkv<<<dim3(1, 512, 24), 256>>>(x, Wq, Wk, Wv);

    // 2. fused attention -> heads_cat (32768 x 512) in slot3
    k_attn<<<dim3(8, 64, 8), 256>>>();

    // 3. output projection: heads_cat @ Wo_flat (512x512) -> slot4
    k_gemm_nn_slots<<<dim3(8, 512), 256>>>(3, Wo, 4, 512, 512, 512, 512, nullptr);

    // 4. BN1 on 2*proj -> slot0 (h)
    k_bnstats<<<dim3(2, 256), 256>>>(4, -1, 2.f);
    k_bnfinal<<<1, 512>>>(n1w, n1b);
    k_bnapply<<<16384, 256>>>(4, -1, 2.f, 0, nullptr);

    // 5. FFN: relu(h @ W1^T + b1) -> slot1 ; @ W2^T + b2 -> slot2
    k_gemm_tn_relu_slots<<<dim3(8, 512), 256>>>(0, ffw1, 1, 512, 512, 512, 512, ffb1);
    k_gemm_tn_slots<<<dim3(8, 512), 256>>>(1, ffw2, 2, 512, 512, 512, 512, ffb2);

    // 6. BN2 on 2*(h + ff2) -> d_out
    k_bnstats<<<dim3(2, 256), 256>>>(0, 2, 2.f);
    k_bnfinal<<<1, 512>>>(n2w, n2b);
    k_bnapply<<<16384, 256>>>(0, 2, 2.f, -1, (float*)d_out);
}

// round 4
// speedup vs baseline: 1.8257x; 1.8257x over previous
#include <cuda_runtime.h>
#include <cuda_bf16.h>
#include <math.h>
#include <stdint.h>

// Problem constants
#define B_BATCH 64
#define N_SEQ   512
#define D_MOD   512
#define H_HEADS 8
#define DK_HEAD 64
#define BN_TOT  32768
#define SLOT    16777216u        // BN_TOT * 512 floats

// Arena slots: 0:Q->h  1:K->ff1  2:V->ff2  3:heads_cat  4:proj
__device__ float g_arena[5u * SLOT];
__device__ float g_psum[256 * 512];
__device__ float g_psq[256 * 512];
__device__ float g_gamma[512];
__device__ float g_beta[512];

// Pre-split bf16 weights (transposed to [n][k], k contiguous, rows of 512):
//  [0, 786432)        : QKV  (24 tiles of 64x512; z = which*8+h)
//  [786432, 1048576)  : Wo_t (512x512)
//  [1048576, 1310720) : ffw1 (512x512, already n-major)
//  [1310720, 1572864) : ffw2
#define WOFF_QKV 0u
#define WOFF_WO  786432u
#define WOFF_FF1 1048576u
#define WOFF_FF2 1310720u
__device__ __align__(128) __nv_bfloat16 g_wbf_hi[1572864];
__device__ __align__(128) __nv_bfloat16 g_wbf_lo[1572864];

// ===========================================================================
// Helpers (all legal on base sm_100 PTX target: HMMA mma.sync + ldmatrix)
// ===========================================================================
__device__ __forceinline__ uint32_t smem_u32(const void* p) {
    uint32_t a;
    asm("{ .reg .u64 t; cvta.to.shared.u64 t, %1; cvt.u32.u64 %0, t; }" : "=r"(a) : "l"(p));
    return a;
}
__device__ __forceinline__ void ldsm_x4(uint32_t* r, uint32_t addr) {
    asm volatile("ldmatrix.sync.aligned.m8n8.x4.shared.b16 {%0,%1,%2,%3}, [%4];"
        : "=r"(r[0]), "=r"(r[1]), "=r"(r[2]), "=r"(r[3]) : "r"(addr));
}
__device__ __forceinline__ void mma16816(float* c, const uint32_t* a, const uint32_t* b) {
    asm volatile("mma.sync.aligned.m16n8k16.row.col.f32.bf16.bf16.f32 "
        "{%0,%1,%2,%3}, {%4,%5,%6,%7}, {%8,%9}, {%0,%1,%2,%3};"
        : "+f"(c[0]), "+f"(c[1]), "+f"(c[2]), "+f"(c[3])
        : "r"(a[0]), "r"(a[1]), "r"(a[2]), "r"(a[3]), "r"(b[0]), "r"(b[1]));
}
__device__ __forceinline__ uint32_t pack2(__nv_bfloat16 a, __nv_bfloat16 b) {
    return (uint32_t)__bfloat16_as_ushort(a) | ((uint32_t)__bfloat16_as_ushort(b) << 16);
}

// ===========================================================================
// HMMA GEMM tile: C[128 x 64] = A[128 x 512] @ Bt[64 x 512]^T (+bias, +relu)
// A fp32 (lda=512), Bt pre-split bf16 hi/lo (rows of 512, k contiguous).
// Split-bf16: C = Ah*Bh + Ah*Bl + Al*Bh  (fp32 accumulate).
// 256 threads = 8 warps (4 m x 2 n), warp tile 32x32, BK=64.
// SMEM 48KB static: Ah[128x128B] Al Bh[64x128B] Bl, XOR-16B swizzled rows.
// ===========================================================================
__device__ void mm_tile(const float* __restrict__ A,
                        const __nv_bfloat16* __restrict__ Bh,
                        const __nv_bfloat16* __restrict__ Bl,
                        float* __restrict__ C, int ldc,
                        const float* __restrict__ bias, int relu, int m0)
{
    __shared__ __align__(1024) char sm[49152];
    const uint32_t sbase = smem_u32(sm);

    const int tid  = threadIdx.x;
    const int lane = tid & 31, wid = tid >> 5;
    const int wm = wid >> 1, wn = wid & 1;       // warp grid 4 x 2
    const int t8 = lane >> 3, lr = lane & 7;     // ldmatrix tile / row-in-tile

    float acc[2][4][4];
#pragma unroll
    for (int i = 0; i < 2; i++)
#pragma unroll
        for (int j = 0; j < 4; j++)
#pragma unroll
            for (int k = 0; k < 4; k++) acc[i][j][k] = 0.f;

    for (int c = 0; c < 8; c++) {
        // ---- stage A chunk (128 x 64 fp32 -> hi/lo bf16, swizzled) ----
        const float* Ac = A + (size_t)m0 * 512 + c * 64;
#pragma unroll
        for (int it = 0; it < 4; it++) {
            int idx = it * 256 + tid;          // 0..1023
            int row = idx >> 3, f8 = idx & 7;  // 8-float group
            const float* p = Ac + (size_t)row * 512 + f8 * 8;
            float4 v0 = *(const float4*)p;
            float4 v1 = *(const float4*)(p + 4);
            __nv_bfloat16 h0 = __float2bfloat16_rn(v0.x), h1 = __float2bfloat16_rn(v0.y);
            __nv_bfloat16 h2 = __float2bfloat16_rn(v0.z), h3 = __float2bfloat16_rn(v0.w);
            __nv_bfloat16 h4 = __float2bfloat16_rn(v1.x), h5 = __float2bfloat16_rn(v1.y);
            __nv_bfloat16 h6 = __float2bfloat16_rn(v1.z), h7 = __float2bfloat16_rn(v1.w);
            uint4 hv = make_uint4(pack2(h0, h1), pack2(h2, h3), pack2(h4, h5), pack2(h6, h7));
            uint4 lv = make_uint4(
                pack2(__float2bfloat16_rn(v0.x - __bfloat162float(h0)),
                      __float2bfloat16_rn(v0.y - __bfloat162float(h1))),
                pack2(__float2bfloat16_rn(v0.z - __bfloat162float(h2)),
                      __float2bfloat16_rn(v0.w - __bfloat162float(h3))),
                pack2(__float2bfloat16_rn(v1.x - __bfloat162float(h4)),
                      __float2bfloat16_rn(v1.y - __bfloat162float(h5))),
                pack2(__float2bfloat16_rn(v1.z - __bfloat162float(h6)),
                      __float2bfloat16_rn(v1.w - __bfloat162float(h7))));
            uint32_t cb = (uint32_t)(f8 * 16) ^ (((uint32_t)row & 7u) << 4);
            *(uint4*)(sm + row * 128 + cb)         = hv;   // Ah @ 0
            *(uint4*)(sm + 16384 + row * 128 + cb) = lv;   // Al @ 16K
        }
        // ---- stage B chunk (64 rows x 64 bf16, hi+lo, swizzled) ----
#pragma unroll
        for (int it = 0; it < 4; it++) {
            int idx = it * 256 + tid;          // 0..1023
            int bufl = idx >> 9;               // 0 = hi, 1 = lo
            int rem  = idx & 511;
            int row = rem >> 3, ch = rem & 7;
            const __nv_bfloat16* src = (bufl ? Bl : Bh) + (size_t)row * 512 + c * 64 + ch * 8;
            uint32_t cb = (uint32_t)(ch * 16) ^ (((uint32_t)row & 7u) << 4);
            *(uint4*)(sm + 32768 + bufl * 8192 + row * 128 + cb) = *(const uint4*)src;
        }
        __syncthreads();

        // ---- compute: 4 k16 steps ----
#pragma unroll
        for (int s = 0; s < 4; s++) {
            uint32_t ah[2][4], al[2][4], bh[2][4], bl[2][4];
#pragma unroll
            for (int msub = 0; msub < 2; msub++) {
                uint32_t row = (uint32_t)(wm * 32 + msub * 16 + ((t8 & 1) << 3) + lr);
                uint32_t cb  = ((uint32_t)s << 5) + (((uint32_t)t8 >> 1) << 4);
                uint32_t a = sbase + row * 128 + (cb ^ ((row & 7u) << 4));
                ldsm_x4(ah[msub], a);
                ldsm_x4(al[msub], a + 16384);
            }
#pragma unroll
            for (int nsub = 0; nsub < 2; nsub++) {
                uint32_t row = (uint32_t)(wn * 32 + nsub * 16 + ((t8 >> 1) << 3) + lr);
                uint32_t cb  = ((uint32_t)s << 5) + (((uint32_t)t8 & 1u) << 4);
                uint32_t a = sbase + 32768 + row * 128 + (cb ^ ((row & 7u) << 4));
                ldsm_x4(bh[nsub], a);
                ldsm_x4(bl[nsub], a + 8192);
            }
#pragma unroll
            for (int msub = 0; msub < 2; msub++)
#pragma unroll
                for (int n8 = 0; n8 < 4; n8++) {
                    const uint32_t* bhp = &bh[n8 >> 1][(n8 & 1) * 2];
                    const uint32_t* blp = &bl[n8 >> 1][(n8 & 1) * 2];
                    mma16816(acc[msub][n8], ah[msub], bhp);
                    mma16816(acc[msub][n8], ah[msub], blp);
                    mma16816(acc[msub][n8], al[msub], bhp);
                }
        }
        __syncthreads();
    }

    // ---- epilogue: acc -> smem (stride 65) -> coalesced gmem ----
    float* ep = (float*)sm;                    // 128 x 65 floats = 33280B
    int g = lane >> 2, tq = lane & 3;
#pragma unroll
    for (int msub = 0; msub < 2; msub++)
#pragma unroll
        for (int n8 = 0; n8 < 4; n8++)
#pragma unroll
            for (int i = 0; i < 4; i++) {
                int row = wm * 32 + msub * 16 + ((i >> 1) << 3) + g;
                int col = wn * 32 + n8 * 8 + tq * 2 + (i & 1);
                ep[row * 65 + col] = acc[msub][n8][i];
            }
    __syncthreads();
    int mr = tid >> 4, kq = tid & 15;
    float4 bb = make_float4(0.f, 0.f, 0.f, 0.f);
    if (bias) bb = *(const float4*)&bias[kq * 4];
#pragma unroll
    for (int it = 0; it < 8; it++) {
        int m = it * 16 + mr;
        float4 o;
        o.x = ep[m * 65 + kq * 4 + 0] + bb.x;
        o.y = ep[m * 65 + kq * 4 + 1] + bb.y;
        o.z = ep[m * 65 + kq * 4 + 2] + bb.z;
        o.w = ep[m * 65 + kq * 4 + 3] + bb.w;
        if (relu) {
            o.x = fmaxf(o.x, 0.f); o.y = fmaxf(o.y, 0.f);
            o.z = fmaxf(o.z, 0.f); o.w = fmaxf(o.w, 0.f);
        }
        *(float4*)(C + (size_t)(m0 + m) * ldc + kq * 4) = o;
    }
}

// QKV: grid (256 m-tiles, 24 z). z -> (which, h). C per-head [m][64].
__global__ __launch_bounds__(256) void k_mm_qkv(const float* __restrict__ x)
{
    int z = blockIdx.y;
    int which = z >> 3, h = z & 7;
    float* C = g_arena + (size_t)which * SLOT + (size_t)h * (BN_TOT * (size_t)DK_HEAD);
    mm_tile(x, g_wbf_hi + (size_t)z * 32768, g_wbf_lo + (size_t)z * 32768,
            C, 64, nullptr, 0, blockIdx.x * 128);
}

// Generic (ldc=512): grid (256 m-tiles, 8 n-tiles)
__global__ __launch_bounds__(256) void k_mm_nt(int aslot, unsigned boff, int cslot,
                                               const float* __restrict__ bias, int relu)
{
    const float* A = g_arena + (size_t)aslot * SLOT;
    float* C = g_arena + (size_t)cslot * SLOT;
    int n0 = blockIdx.y * 64;
    mm_tile(A, g_wbf_hi + boff + (size_t)n0 * 512, g_wbf_lo + boff + (size_t)n0 * 512,
            C + n0, 512, bias ? bias + n0 : nullptr, relu, blockIdx.x * 128);
}

// ===========================================================================
// Weight prep: transpose (where needed) + split fp32 -> bf16 hi/lo
// ===========================================================================
__device__ __forceinline__ void wsplit(size_t o, float v) {
    __nv_bfloat16 h = __float2bfloat16_rn(v);
    g_wbf_hi[o] = h;
    g_wbf_lo[o] = __float2bfloat16_rn(v - __bfloat162float(h));
}
__global__ __launch_bounds__(256) void k_prep_qkv(const float* __restrict__ Wq,
    const float* __restrict__ Wk, const float* __restrict__ Wv)
{
    int z = blockIdx.y, which = z >> 3, h = z & 7;
    const float* W = (which == 0 ? Wq : (which == 1 ? Wk : Wv)) + (size_t)h * 32768;
    int i = blockIdx.x * 256 + threadIdx.x;       // 32768 per z
    int dk = i >> 9, dd = i & 511;
    wsplit((size_t)WOFF_QKV + (size_t)z * 32768 + i, W[dd * 64 + dk]);
}
__global__ __launch_bounds__(256) void k_prep_wo(const float* __restrict__ Wo)
{
    int i = blockIdx.x * 256 + threadIdx.x;       // 262144
    int dd = i >> 9, hdk = i & 511;
    wsplit((size_t)WOFF_WO + i, Wo[hdk * 512 + dd]);
}
__global__ __launch_bounds__(256) void k_prep_ff(const float* __restrict__ w1,
                                                 const float* __restrict__ w2)
{
    int i = blockIdx.x * 256 + threadIdx.x;       // 524288
    float v = (i < 262144) ? w1[i] : w2[i - 262144];
    wsplit((size_t)WOFF_FF1 + i, v);
}

// ===========================================================================
// Fused fp32 flash attention (unchanged from passing round)
// ===========================================================================
__global__ __launch_bounds__(256) void k_attn()
{
    const int h = blockIdx.z, b = blockIdx.y, q0 = blockIdx.x * 64;
    const size_t hb = ((size_t)h * BN_TOT + (size_t)b * N_SEQ) * DK_HEAD;
    const float* Q = g_arena + 0 * (size_t)SLOT + hb;
    const float* K = g_arena + 1 * (size_t)SLOT + hb;
    const float* V = g_arena + 2 * (size_t)SLOT + hb;
    float* OUT = g_arena + 3 * (size_t)SLOT;

    __shared__ float Qst[64][64];
    __shared__ float KPs[64][64];
    __shared__ float Vs[64][64];

    const int tid = threadIdx.x;
    const int tx = tid & 15, ty = tid >> 4;
    const int lr  = tid >> 2;
    const int lcb = (tid & 3) * 16;

#pragma unroll
    for (int u = 0; u < 4; u++) {
        float4 v = *(const float4*)(Q + (size_t)(q0 + lr) * DK_HEAD + lcb + u * 4);
        Qst[lcb + u * 4 + 0][lr] = v.x; Qst[lcb + u * 4 + 1][lr] = v.y;
        Qst[lcb + u * 4 + 2][lr] = v.z; Qst[lcb + u * 4 + 3][lr] = v.w;
    }

    float m_[4], l_[4], acc[4][4];
#pragma unroll
    for (int i = 0; i < 4; i++) {
        m_[i] = -1e30f; l_[i] = 0.f;
#pragma unroll
        for (int j = 0; j < 4; j++) acc[i][j] = 0.f;
    }
    const float scale = 0.125f;

    for (int kt = 0; kt < 8; kt++) {
        __syncthreads();
        const float* Kt = K + (size_t)kt * 64 * DK_HEAD;
        const float* Vt = V + (size_t)kt * 64 * DK_HEAD;
#pragma unroll
        for (int u = 0; u < 4; u++) {
            float4 v = *(const float4*)(Kt + (size_t)lr * DK_HEAD + lcb + u * 4);
            KPs[lcb + u * 4 + 0][lr] = v.x; KPs[lcb + u * 4 + 1][lr] = v.y;
            KPs[lcb + u * 4 + 2][lr] = v.z; KPs[lcb + u * 4 + 3][lr] = v.w;
            float4 w = *(const float4*)(Vt + (size_t)lr * DK_HEAD + lcb + u * 4);
            *(float4*)&Vs[lr][lcb + u * 4] = w;
        }
        __syncthreads();

        float s[4][4];
#pragma unroll
        for (int i = 0; i < 4; i++)
#pragma unroll
            for (int j = 0; j < 4; j++) s[i][j] = 0.f;
#pragma unroll 8
        for (int dd = 0; dd < 64; dd++) {
            float4 a4 = *(const float4*)&Qst[dd][ty * 4];
            float4 b4 = *(const float4*)&KPs[dd][tx * 4];
            float a[4] = {a4.x, a4.y, a4.z, a4.w};
            float bb[4] = {b4.x, b4.y, b4.z, b4.w};
#pragma unroll
            for (int i = 0; i < 4; i++)
#pragma unroll
                for (int j = 0; j < 4; j++)
                    s[i][j] += a[i] * bb[j];
        }

        float alpha[4];
#pragma unroll
        for (int i = 0; i < 4; i++) {
            float rm = -1e30f;
#pragma unroll
            for (int j = 0; j < 4; j++) { s[i][j] *= scale; rm = fmaxf(rm, s[i][j]); }
#pragma unroll
            for (int msk = 8; msk >= 1; msk >>= 1)
                rm = fmaxf(rm, __shfl_xor_sync(0xffffffffu, rm, msk));
            float mnew = fmaxf(m_[i], rm);
            alpha[i] = __expf(m_[i] - mnew);
            float rs = 0.f;
#pragma unroll
            for (int j = 0; j < 4; j++) { s[i][j] = __expf(s[i][j] - mnew); rs += s[i][j]; }
#pragma unroll
            for (int msk = 8; msk >= 1; msk >>= 1)
                rs += __shfl_xor_sync(0xffffffffu, rs, msk);
            l_[i] = l_[i] * alpha[i] + rs;
            m_[i] = mnew;
#pragma unroll
            for (int j = 0; j < 4; j++) acc[i][j] *= alpha[i];
        }

        __syncthreads();
#pragma unroll
        for (int i = 0; i < 4; i++)
            *(float4*)&KPs[ty * 4 + i][tx * 4] =
                make_float4(s[i][0], s[i][1], s[i][2], s[i][3]);
        __syncthreads();

#pragma unroll 8
        for (int kj = 0; kj < 64; kj++) {
            float4 b4 = *(const float4*)&Vs[kj][tx * 4];
            float bb[4] = {b4.x, b4.y, b4.z, b4.w};
#pragma unroll
            for (int i = 0; i < 4; i++) {
                float a = KPs[ty * 4 + i][kj];
#pragma unroll
                for (int j = 0; j < 4; j++)
                    acc[i][j] += a * bb[j];
            }
        }
    }

#pragma unroll
    for (int i = 0; i < 4; i++) {
        float inv = 1.f / l_[i];
        size_t row = (size_t)b * N_SEQ + q0 + ty * 4 + i;
        *(float4*)&OUT[row * D_MOD + h * DK_HEAD + tx * 4] =
            make_float4(acc[i][0] * inv, acc[i][1] * inv,
                        acc[i][2] * inv, acc[i][3] * inv);
    }
}

// ===========================================================================
// Deterministic two-stage BatchNorm (unchanged)
// ===========================================================================
__global__ __launch_bounds__(256) void k_bnstats(int aslot, int bslot, float scale)
{
    const float* A = g_arena + (size_t)aslot * SLOT;
    const float* Bopt = (bslot >= 0) ? (g_arena + (size_t)bslot * SLOT) : nullptr;
    int c = blockIdx.x * 256 + threadIdx.x;
    int chunk = blockIdx.y;
    int r0 = chunk * 128;
    float s = 0.f, q = 0.f;
    for (int r = r0; r < r0 + 128; r++) {
        float t = A[(size_t)r * 512 + c];
        if (Bopt) t += Bopt[(size_t)r * 512 + c];
        t *= scale;
        s += t; q += t * t;
    }
    g_psum[chunk * 512 + c] = s;
    g_psq[chunk * 512 + c]  = q;
}

__global__ __launch_bounds__(512) void k_bnfinal(const float* __restrict__ w,
                                                 const float* __restrict__ bias)
{
    int c = threadIdx.x;
    float s = 0.f, q = 0.f;
    for (int i = 0; i < 256; i++) { s += g_psum[i * 512 + c]; q += g_psq[i * 512 + c]; }
    float m   = s * (1.f / 32768.f);
    float var = q * (1.f / 32768.f) - m * m;
    float inv = rsqrtf(var + 1e-5f);
    float g   = inv * w[c];
    g_gamma[c] = g;
    g_beta[c]  = bias[c] - m * g;
}

__global__ __launch_bounds__(256) void k_bnapply(int aslot, int bslot, float scale,
                                                 int outslot, float* __restrict__ ext_out)
{
    const float* A = g_arena + (size_t)aslot * SLOT;
    const float* Bopt = (bslot >= 0) ? (g_arena + (size_t)bslot * SLOT) : nullptr;
    float* out = (outslot >= 0) ? (g_arena + (size_t)outslot * SLOT) : ext_out;
    size_t i = ((size_t)blockIdx.x * 256 + threadIdx.x) * 4;
    int c = (int)(i & 511);
    float4 a = *(const float4*)(A + i);
    if (Bopt) {
        float4 b = *(const float4*)(Bopt + i);
        a.x += b.x; a.y += b.y; a.z += b.z; a.w += b.w;
    }
    float4 g = *(const float4*)&g_gamma[c];
    float4 bt = *(const float4*)&g_beta[c];
    float4 y;
    y.x = scale * a.x * g.x + bt.x;
    y.y = scale * a.y * g.y + bt.y;
    y.z = scale * a.z * g.z + bt.z;
    y.w = scale * a.w * g.w + bt.w;
    *(float4*)(out + i) = y;
}

// ===========================================================================
// Pipeline (kernel launches only)
// ===========================================================================
extern "C" void kernel_launch(void* const* d_in, const int* in_sizes, int n_in,
                              void* d_out, int out_size)
{
    const float* x    = (const float*)d_in[0];
    const float* Wq   = (const float*)d_in[1];
    const float* Wk   = (const float*)d_in[2];
    const float* Wv   = (const float*)d_in[3];
    const float* Wo   = (const float*)d_in[4];
    const float* n1w  = (const float*)d_in[5];
    const float* n1b  = (const float*)d_in[6];
    const float* n2w  = (const float*)d_in[7];
    const float* n2b  = (const float*)d_in[8];
    const float* ffw1 = (const float*)d_in[9];
    const float* ffb1 = (const float*)d_in[10];
    const float* ffw2 = (const float*)d_in[11];
    const float* ffb2 = (const float*)d_in[12];

    // 0. weight prep: transpose + bf16 hi/lo split
    k_prep_qkv<<<dim3(128, 24), 256>>>(Wq, Wk, Wv);
    k_prep_wo<<<1024, 256>>>(Wo);
    k_prep_ff<<<2048, 256>>>(ffw1, ffw2);

    // 1. QKV projections (HMMA): slots 0/1/2, per-head [m][64]
    k_mm_qkv<<<dim3(256, 24), 256>>>(x);

    // 2. fused attention -> heads_cat slot3
    k_attn<<<dim3(8, 64, 8), 256>>>();

    // 3. output projection -> slot4
    k_mm_nt<<<dim3(256, 8), 256>>>(3, WOFF_WO, 4, nullptr, 0);

    // 4. BN1 on 2*proj -> slot0 (h)
    k_bnstats<<<dim3(2, 256), 256>>>(4, -1, 2.f);
    k_bnfinal<<<1, 512>>>(n1w, n1b);
    k_bnapply<<<16384, 256>>>(4, -1, 2.f, 0, nullptr);

    // 5. FFN
    k_mm_nt<<<dim3(256, 8), 256>>>(0, WOFF_FF1, 1, ffb1, 1);
    k_mm_nt<<<dim3(256, 8), 256>>>(1, WOFF_FF2, 2, ffb2, 0);

    // 6. BN2 on 2*(h + ff2) -> d_out
    k_bnstats<<<dim3(2, 256), 256>>>(0, 2, 2.f);
    k_bnfinal<<<1, 512>>>(n2w, n2b);
    k_bnapply<<<16384, 256>>>(0, 2, 2.f, -1, (float*)d_out);
}

// round 8
// speedup vs baseline: 2.4232x; 1.3273x over previous
#include <cuda_runtime.h>
#include <cuda_bf16.h>
#include <math.h>
#include <stdint.h>

// Problem constants
#define B_BATCH 64
#define N_SEQ   512
#define D_MOD   512
#define H_HEADS 8
#define DK_HEAD 64
#define BN_TOT  32768
#define SLOT    16777216u        // BN_TOT * 512 floats

// Arena slots: 0:h  1:ff1  2:ff2  3:heads_cat  4:proj
__device__ float g_arena[5u * SLOT];
__device__ float g_psum[256 * 512];
__device__ float g_psq[256 * 512];
__device__ float g_gamma[512];
__device__ float g_beta[512];

// Pre-split bf16 weights (transposed to [n][k], k contiguous, rows of 512):
#define WOFF_QKV 0u
#define WOFF_WO  786432u
#define WOFF_FF1 1048576u
#define WOFF_FF2 1310720u
__device__ __align__(128) __nv_bfloat16 g_wbf_hi[1572864];
__device__ __align__(128) __nv_bfloat16 g_wbf_lo[1572864];

// Pre-split bf16 activations
__device__ __align__(128) __nv_bfloat16 g_xh[16777216];  // x hi  [m][512]
__device__ __align__(128) __nv_bfloat16 g_xl[16777216];  // x lo
// Q,K: [h][m][64]   Vt: [h][b][dv][512]
__device__ __align__(128) __nv_bfloat16 g_qh[16777216];
__device__ __align__(128) __nv_bfloat16 g_ql[16777216];
__device__ __align__(128) __nv_bfloat16 g_kh[16777216];
__device__ __align__(128) __nv_bfloat16 g_kl[16777216];
__device__ __align__(128) __nv_bfloat16 g_vth[16777216];
__device__ __align__(128) __nv_bfloat16 g_vtl[16777216];

// ===========================================================================
// Helpers (base sm_100 PTX: HMMA mma.sync + ldmatrix)
// ===========================================================================
__device__ __forceinline__ uint32_t smem_u32(const void* p) {
    uint32_t a;
    asm("{ .reg .u64 t; cvta.to.shared.u64 t, %1; cvt.u32.u64 %0, t; }" : "=r"(a) : "l"(p));
    return a;
}
__device__ __forceinline__ void ldsm_x4(uint32_t* r, uint32_t addr) {
    asm volatile("ldmatrix.sync.aligned.m8n8.x4.shared.b16 {%0,%1,%2,%3}, [%4];"
        : "=r"(r[0]), "=r"(r[1]), "=r"(r[2]), "=r"(r[3]) : "r"(addr));
}
__device__ __forceinline__ void mma16816(float* c, const uint32_t* a, const uint32_t* b) {
    asm volatile("mma.sync.aligned.m16n8k16.row.col.f32.bf16.bf16.f32 "
        "{%0,%1,%2,%3}, {%4,%5,%6,%7}, {%8,%9}, {%0,%1,%2,%3};"
        : "+f"(c[0]), "+f"(c[1]), "+f"(c[2]), "+f"(c[3])
        : "r"(a[0]), "r"(a[1]), "r"(a[2]), "r"(a[3]), "r"(b[0]), "r"(b[1]));
}
__device__ __forceinline__ uint32_t pack2(__nv_bfloat16 a, __nv_bfloat16 b) {
    return (uint32_t)__bfloat16_as_ushort(a) | ((uint32_t)__bfloat16_as_ushort(b) << 16);
}
__device__ __forceinline__ __nv_bfloat16 bhi(float v) { return __float2bfloat16_rn(v); }
__device__ __forceinline__ __nv_bfloat16 blo(float v, __nv_bfloat16 h) {
    return __float2bfloat16_rn(v - __bfloat162float(h));
}
// 128B-row swizzle (k64 tiles)
__device__ __forceinline__ uint32_t sw128b(uint32_t row, uint32_t cb) {
    return row * 128 + (cb ^ ((row & 7u) << 4));
}
// paired-row swizzle for 64B (k32) tiles packed two rows per 128B line
__device__ __forceinline__ uint32_t sw32b(uint32_t row, uint32_t cb) {
    return (row >> 1) * 128 + ((((row & 1u) << 6) | cb) ^ (((row >> 1) & 7u) << 4));
}

// ===========================================================================
// Fused QKV: block = (m-tile 128, head h). A (bf16 hi/lo of x) staged ONCE per
// k-chunk, shared by Q/K/V weight tiles. BK=32, 16 chunks. Outputs bf16 hi/lo
// Q,K ([h][m][64]) and V transposed ([h][b][dv][512]). 8 warps (4m x 2n).
// ===========================================================================
__global__ __launch_bounds__(256) void k_mm_qkv3()
{
    __shared__ __align__(1024) char sm[40960];
    const uint32_t sb = smem_u32(sm);
    const int h = blockIdx.y;
    const int m0 = blockIdx.x * 128;
    const int tid = threadIdx.x, lane = tid & 31, wid = tid >> 5;
    const int wm = wid >> 1, wn = wid & 1;
    const int t8 = lane >> 3, lr = lane & 7;

    float acc[3][2][4][4];
#pragma unroll
    for (int q = 0; q < 3; q++)
#pragma unroll
        for (int i = 0; i < 2; i++)
#pragma unroll
            for (int j = 0; j < 4; j++)
#pragma unroll
                for (int k = 0; k < 4; k++) acc[q][i][j][k] = 0.f;

    for (int c = 0; c < 16; c++) {
        // stage A (128 x 32, hi+lo): bufs at 0 / 8192
#pragma unroll
        for (int it = 0; it < 4; it++) {
            int idx = it * 256 + tid;            // 0..1023
            int arr = idx >> 9, rem = idx & 511;
            int row = rem >> 2, f8 = rem & 3;
            const __nv_bfloat16* src = (arr ? g_xl : g_xh)
                + (size_t)(m0 + row) * 512 + c * 32 + f8 * 8;
            *(uint4*)(sm + arr * 8192 + sw32b(row, f8 * 16)) = *(const uint4*)src;
        }
        // stage B (3 which x 64 x 32, hi+lo): base 16384 + which*8192 + hl*4096
#pragma unroll
        for (int it = 0; it < 6; it++) {
            int idx = it * 256 + tid;            // 0..1535
            int which = idx >> 9, rem = idx & 511;
            int hl = rem >> 8, r2 = rem & 255;
            int row = r2 >> 2, f8 = r2 & 3;
            const __nv_bfloat16* src = (hl ? g_wbf_lo : g_wbf_hi)
                + (size_t)(which * 8 + h) * 32768 + (size_t)row * 512 + c * 32 + f8 * 8;
            *(uint4*)(sm + 16384 + which * 8192 + hl * 4096 + sw32b(row, f8 * 16))
                = *(const uint4*)src;
        }
        __syncthreads();

#pragma unroll
        for (int s = 0; s < 2; s++) {
            uint32_t ah[2][4], al[2][4];
#pragma unroll
            for (int msub = 0; msub < 2; msub++) {
                uint32_t row = (uint32_t)(wm * 32 + msub * 16 + ((t8 & 1) << 3) + lr);
                uint32_t cb  = ((uint32_t)s << 5) + (((uint32_t)t8 >> 1) << 4);
                uint32_t off = sw32b(row, cb);
                ldsm_x4(ah[msub], sb + off);
                ldsm_x4(al[msub], sb + 8192 + off);
            }
#pragma unroll
            for (int q = 0; q < 3; q++) {
                uint32_t bh[2][4], bl[2][4];
#pragma unroll
                for (int nsub = 0; nsub < 2; nsub++) {
                    uint32_t row = (uint32_t)(wn * 32 + nsub * 16 + ((t8 >> 1) << 3) + lr);
                    uint32_t cb  = ((uint32_t)s << 5) + (((uint32_t)t8 & 1u) << 4);
                    uint32_t off = sw32b(row, cb);
                    ldsm_x4(bh[nsub], sb + 16384 + q * 8192 + off);
                    ldsm_x4(bl[nsub], sb + 16384 + q * 8192 + 4096 + off);
                }
#pragma unroll
                for (int msub = 0; msub < 2; msub++)
#pragma unroll
                    for (int n8 = 0; n8 < 4; n8++) {
                        const uint32_t* bhp = &bh[n8 >> 1][(n8 & 1) * 2];
                        const uint32_t* blp = &bl[n8 >> 1][(n8 & 1) * 2];
                        mma16816(acc[q][msub][n8], ah[msub], bhp);
                        mma16816(acc[q][msub][n8], ah[msub], blp);
                        mma16816(acc[q][msub][n8], al[msub], bhp);
                    }
            }
        }
        __syncthreads();
    }

    // epilogue per which: acc -> ep smem -> bf16 hi/lo global
    float* ep = (float*)sm;                     // 128 x 65
    const int g = lane >> 2, tq = lane & 3;
    const int b = m0 >> 9, n0 = m0 & 511;
    const size_t vtoff = (size_t)(h * 64 + b) * 32768;

#pragma unroll
    for (int q = 0; q < 3; q++) {
        __syncthreads();
#pragma unroll
        for (int msub = 0; msub < 2; msub++)
#pragma unroll
            for (int n8 = 0; n8 < 4; n8++)
#pragma unroll
                for (int i = 0; i < 4; i++) {
                    int row = wm * 32 + msub * 16 + ((i >> 1) << 3) + g;
                    int col = wn * 32 + n8 * 8 + tq * 2 + (i & 1);
                    ep[row * 65 + col] = acc[q][msub][n8][i];
                }
        __syncthreads();
        if (q < 2) {
            __nv_bfloat16* Dh = q ? g_kh : g_qh;
            __nv_bfloat16* Dl = q ? g_kl : g_ql;
            int mr = tid >> 4, kq = tid & 15;
#pragma unroll
            for (int it = 0; it < 8; it++) {
                int m = it * 16 + mr;
                // scalar smem reads (stride-65 rows are NOT float4-aligned)
                float fx = ep[m * 65 + kq * 4 + 0];
                float fy = ep[m * 65 + kq * 4 + 1];
                float fz = ep[m * 65 + kq * 4 + 2];
                float fw = ep[m * 65 + kq * 4 + 3];
                __nv_bfloat16 h0 = bhi(fx), h1 = bhi(fy), h2 = bhi(fz), h3 = bhi(fw);
                uint2 hv = make_uint2(pack2(h0, h1), pack2(h2, h3));
                uint2 lv = make_uint2(pack2(blo(fx, h0), blo(fy, h1)),
                                      pack2(blo(fz, h2), blo(fw, h3)));
                size_t o = ((size_t)h * BN_TOT + (size_t)(m0 + m)) * 64 + kq * 4;
                *(uint2*)(Dh + o) = hv;
                *(uint2*)(Dl + o) = lv;
            }
        } else {
            // V transposed: [dv][n]
            int nn = (tid & 15) * 8;
#pragma unroll
            for (int p = 0; p < 4; p++) {
                int dv = p * 16 + (tid >> 4);
                __nv_bfloat16 hs[8], ls[8];
#pragma unroll
                for (int j = 0; j < 8; j++) {
                    float v = ep[(nn + j) * 65 + dv];
                    hs[j] = bhi(v);
                    ls[j] = blo(v, hs[j]);
                }
                size_t o = vtoff + (size_t)dv * 512 + n0 + nn;
                *(uint4*)(g_vth + o) = make_uint4(pack2(hs[0], hs[1]), pack2(hs[2], hs[3]),
                                                  pack2(hs[4], hs[5]), pack2(hs[6], hs[7]));
                *(uint4*)(g_vtl + o) = make_uint4(pack2(ls[0], ls[1]), pack2(ls[2], ls[3]),
                                                  pack2(ls[4], ls[5]), pack2(ls[6], ls[7]));
            }
        }
    }
}

// ===========================================================================
// HMMA flash attention. Block = (q-tile 128, b, h), 8 warps, warp = 16 q rows
// covering all 64 keys of a chunk. Split-bf16 for QK^T and PV. P comes from
// S accumulators in-register. Output heads (fp32) -> slot3.
// ===========================================================================
__global__ __launch_bounds__(256) void k_attn_mma()
{
    __shared__ __align__(1024) char sm[33536];
    const uint32_t sb = smem_u32(sm);
    const int h = blockIdx.z, b = blockIdx.y, q0 = blockIdx.x * 128;
    const int tid = threadIdx.x, lane = tid & 31, w = tid >> 5;
    const int t8 = lane >> 3, lr = lane & 7;

    const size_t qbase = ((size_t)h * BN_TOT + (size_t)b * 512 + q0) * 64;
    const size_t kbase = ((size_t)h * BN_TOT + (size_t)b * 512) * 64;
    const size_t vtoff = (size_t)(h * 64 + b) * 32768;

    // stage Q (128 x 64 hi at 0, lo at 16384)
#pragma unroll
    for (int it = 0; it < 8; it++) {
        int idx = it * 256 + tid;
        int arr = idx >> 10, rem = idx & 1023;
        int row = rem >> 3, f8 = rem & 7;
        const __nv_bfloat16* src = (arr ? g_ql : g_qh) + qbase + (size_t)row * 64 + f8 * 8;
        *(uint4*)(sm + arr * 16384 + sw128b(row, f8 * 16)) = *(const uint4*)src;
    }
    __syncthreads();

    uint32_t qh[4][4], ql[4][4];
#pragma unroll
    for (int s = 0; s < 4; s++) {
        uint32_t row = (uint32_t)(w * 16 + ((t8 & 1) << 3) + lr);
        uint32_t cb  = ((uint32_t)s << 5) + (((uint32_t)t8 >> 1) << 4);
        uint32_t off = sw128b(row, cb);
        ldsm_x4(qh[s], sb + off);
        ldsm_x4(ql[s], sb + 16384 + off);
    }
    __syncthreads();

    float o[8][4];
#pragma unroll
    for (int n8 = 0; n8 < 8; n8++)
#pragma unroll
        for (int i = 0; i < 4; i++) o[n8][i] = 0.f;
    float m0_ = -1e30f, m1_ = -1e30f, l0 = 0.f, l1 = 0.f;

    for (int kt = 0; kt < 8; kt++) {
        // stage K chunk (hi 0, lo 8192) and Vt chunk (hi 16384, lo 24576)
#pragma unroll
        for (int it = 0; it < 8; it++) {
            int idx = it * 256 + tid;
            int arr = idx >> 9, rem = idx & 511;
            int row = rem >> 3, f8 = rem & 7;
            const __nv_bfloat16* src;
            if (arr == 0)      src = g_kh  + kbase + (size_t)(kt * 64 + row) * 64 + f8 * 8;
            else if (arr == 1) src = g_kl  + kbase + (size_t)(kt * 64 + row) * 64 + f8 * 8;
            else if (arr == 2) src = g_vth + vtoff + (size_t)row * 512 + kt * 64 + f8 * 8;
            else               src = g_vtl + vtoff + (size_t)row * 512 + kt * 64 + f8 * 8;
            *(uint4*)(sm + arr * 8192 + sw128b(row, f8 * 16)) = *(const uint4*)src;
        }
        __syncthreads();

        // S = Q K^T (split-bf16)
        float s[8][4];
#pragma unroll
        for (int n8 = 0; n8 < 8; n8++)
#pragma unroll
            for (int i = 0; i < 4; i++) s[n8][i] = 0.f;
#pragma unroll
        for (int ks = 0; ks < 4; ks++) {
            uint32_t bh[4][4], bl[4][4];
#pragma unroll
            for (int nsub = 0; nsub < 4; nsub++) {
                uint32_t row = (uint32_t)(nsub * 16 + ((t8 >> 1) << 3) + lr);
                uint32_t cb  = ((uint32_t)ks << 5) + (((uint32_t)t8 & 1u) << 4);
                uint32_t off = sw128b(row, cb);
                ldsm_x4(bh[nsub], sb + off);
                ldsm_x4(bl[nsub], sb + 8192 + off);
            }
#pragma unroll
            for (int n8 = 0; n8 < 8; n8++) {
                const uint32_t* bhp = &bh[n8 >> 1][(n8 & 1) * 2];
                const uint32_t* blp = &bl[n8 >> 1][(n8 & 1) * 2];
                mma16816(s[n8], qh[ks], bhp);
                mma16816(s[n8], qh[ks], blp);
                mma16816(s[n8], ql[ks], bhp);
            }
        }

        // online softmax (rows r0 = lane>>2, r1 = r0+8; warp-local)
        float mx0 = -1e30f, mx1 = -1e30f;
#pragma unroll
        for (int n8 = 0; n8 < 8; n8++) {
            s[n8][0] *= 0.125f; s[n8][1] *= 0.125f; s[n8][2] *= 0.125f; s[n8][3] *= 0.125f;
            mx0 = fmaxf(mx0, fmaxf(s[n8][0], s[n8][1]));
            mx1 = fmaxf(mx1, fmaxf(s[n8][2], s[n8][3]));
        }
        mx0 = fmaxf(mx0, __shfl_xor_sync(0xffffffffu, mx0, 1));
        mx0 = fmaxf(mx0, __shfl_xor_sync(0xffffffffu, mx0, 2));
        mx1 = fmaxf(mx1, __shfl_xor_sync(0xffffffffu, mx1, 1));
        mx1 = fmaxf(mx1, __shfl_xor_sync(0xffffffffu, mx1, 2));
        float mn0 = fmaxf(m0_, mx0), mn1 = fmaxf(m1_, mx1);
        float a0 = __expf(m0_ - mn0), a1 = __expf(m1_ - mn1);
        m0_ = mn0; m1_ = mn1;
        float rs0 = 0.f, rs1 = 0.f;
#pragma unroll
        for (int n8 = 0; n8 < 8; n8++) {
            s[n8][0] = __expf(s[n8][0] - mn0); s[n8][1] = __expf(s[n8][1] - mn0);
            s[n8][2] = __expf(s[n8][2] - mn1); s[n8][3] = __expf(s[n8][3] - mn1);
            rs0 += s[n8][0] + s[n8][1];
            rs1 += s[n8][2] + s[n8][3];
        }
        rs0 += __shfl_xor_sync(0xffffffffu, rs0, 1);
        rs0 += __shfl_xor_sync(0xffffffffu, rs0, 2);
        rs1 += __shfl_xor_sync(0xffffffffu, rs1, 1);
        rs1 += __shfl_xor_sync(0xffffffffu, rs1, 2);
        l0 = l0 * a0 + rs0;
        l1 = l1 * a1 + rs1;
#pragma unroll
        for (int n8 = 0; n8 < 8; n8++) {
            o[n8][0] *= a0; o[n8][1] *= a0; o[n8][2] *= a1; o[n8][3] *= a1;
        }

        // P fragments from S accumulators (hi/lo split)
        uint32_t ph[4][4], pl[4][4];
#pragma unroll
        for (int ks = 0; ks < 4; ks++) {
            int na = 2 * ks, nb = 2 * ks + 1;
            __nv_bfloat16 h0 = bhi(s[na][0]), h1 = bhi(s[na][1]),
                          h2 = bhi(s[na][2]), h3 = bhi(s[na][3]);
            __nv_bfloat16 h4 = bhi(s[nb][0]), h5 = bhi(s[nb][1]),
                          h6 = bhi(s[nb][2]), h7 = bhi(s[nb][3]);
            ph[ks][0] = pack2(h0, h1); ph[ks][1] = pack2(h2, h3);
            ph[ks][2] = pack2(h4, h5); ph[ks][3] = pack2(h6, h7);
            pl[ks][0] = pack2(blo(s[na][0], h0), blo(s[na][1], h1));
            pl[ks][1] = pack2(blo(s[na][2], h2), blo(s[na][3], h3));
            pl[ks][2] = pack2(blo(s[nb][0], h4), blo(s[nb][1], h5));
            pl[ks][3] = pack2(blo(s[nb][2], h6), blo(s[nb][3], h7));
        }

        // O += P Vt (split-bf16)
#pragma unroll
        for (int ks = 0; ks < 4; ks++) {
            uint32_t vh[4][4], vl[4][4];
#pragma unroll
            for (int nsub = 0; nsub < 4; nsub++) {
                uint32_t row = (uint32_t)(nsub * 16 + ((t8 >> 1) << 3) + lr);
                uint32_t cb  = ((uint32_t)ks << 5) + (((uint32_t)t8 & 1u) << 4);
                uint32_t off = sw128b(row, cb);
                ldsm_x4(vh[nsub], sb + 16384 + off);
                ldsm_x4(vl[nsub], sb + 24576 + off);
            }
#pragma unroll
            for (int n8 = 0; n8 < 8; n8++) {
                const uint32_t* vhp = &vh[n8 >> 1][(n8 & 1) * 2];
                const uint32_t* vlp = &vl[n8 >> 1][(n8 & 1) * 2];
                mma16816(o[n8], ph[ks], vhp);
                mma16816(o[n8], ph[ks], vlp);
                mma16816(o[n8], pl[ks], vhp);
            }
        }
        __syncthreads();
    }

    // epilogue: normalize, write heads (fp32) to slot3
    float inv0 = 1.f / l0, inv1 = 1.f / l1;
    float* ep = (float*)sm;
    int r0 = lane >> 2, c2 = (lane & 3) * 2;
#pragma unroll
    for (int n8 = 0; n8 < 8; n8++) {
        ep[(w * 16 + r0) * 65 + n8 * 8 + c2]     = o[n8][0] * inv0;
        ep[(w * 16 + r0) * 65 + n8 * 8 + c2 + 1] = o[n8][1] * inv0;
        ep[(w * 16 + r0 + 8) * 65 + n8 * 8 + c2]     = o[n8][2] * inv1;
        ep[(w * 16 + r0 + 8) * 65 + n8 * 8 + c2 + 1] = o[n8][3] * inv1;
    }
    __syncthreads();
    float* OUT = g_arena + 3 * (size_t)SLOT;
    int mr = tid >> 4, kq = tid & 15;
#pragma unroll
    for (int it = 0; it < 8; it++) {
        int m = it * 16 + mr;
        // scalar smem reads (stride-65 rows are NOT float4-aligned)
        float4 f;
        f.x = ep[m * 65 + kq * 4 + 0];
        f.y = ep[m * 65 + kq * 4 + 1];
        f.z = ep[m * 65 + kq * 4 + 2];
        f.w = ep[m * 65 + kq * 4 + 3];
        size_t row = (size_t)b * 512 + q0 + m;
        *(float4*)&OUT[row * 512 + h * 64 + kq * 4] = f;
    }
}

// ===========================================================================
// Generic HMMA GEMM tile (unchanged from R4): C[128x64] = A[128x512] @ Bt^T
// ===========================================================================
__device__ void mm_tile(const float* __restrict__ A,
                        const __nv_bfloat16* __restrict__ Bh,
                        const __nv_bfloat16* __restrict__ Bl,
                        float* __restrict__ C, int ldc,
                        const float* __restrict__ bias, int relu, int m0)
{
    __shared__ __align__(1024) char sm[49152];
    const uint32_t sbase = smem_u32(sm);
    const int tid  = threadIdx.x;
    const int lane = tid & 31, wid = tid >> 5;
    const int wm = wid >> 1, wn = wid & 1;
    const int t8 = lane >> 3, lr = lane & 7;

    float acc[2][4][4];
#pragma unroll
    for (int i = 0; i < 2; i++)
#pragma unroll
        for (int j = 0; j < 4; j++)
#pragma unroll
            for (int k = 0; k < 4; k++) acc[i][j][k] = 0.f;

    for (int c = 0; c < 8; c++) {
        const float* Ac = A + (size_t)m0 * 512 + c * 64;
#pragma unroll
        for (int it = 0; it < 4; it++) {
            int idx = it * 256 + tid;
            int row = idx >> 3, f8 = idx & 7;
            const float* p = Ac + (size_t)row * 512 + f8 * 8;
            float4 v0 = *(const float4*)p;
            float4 v1 = *(const float4*)(p + 4);
            __nv_bfloat16 h0 = bhi(v0.x), h1 = bhi(v0.y), h2 = bhi(v0.z), h3 = bhi(v0.w);
            __nv_bfloat16 h4 = bhi(v1.x), h5 = bhi(v1.y), h6 = bhi(v1.z), h7 = bhi(v1.w);
            uint4 hv = make_uint4(pack2(h0, h1), pack2(h2, h3), pack2(h4, h5), pack2(h6, h7));
            uint4 lv = make_uint4(
                pack2(blo(v0.x, h0), blo(v0.y, h1)), pack2(blo(v0.z, h2), blo(v0.w, h3)),
                pack2(blo(v1.x, h4), blo(v1.y, h5)), pack2(blo(v1.z, h6), blo(v1.w, h7)));
            uint32_t cb = (uint32_t)(f8 * 16) ^ (((uint32_t)row & 7u) << 4);
            *(uint4*)(sm + row * 128 + cb)         = hv;
            *(uint4*)(sm + 16384 + row * 128 + cb) = lv;
        }
#pragma unroll
        for (int it = 0; it < 4; it++) {
            int idx = it * 256 + tid;
            int bufl = idx >> 9;
            int rem  = idx & 511;
            int row = rem >> 3, ch = rem & 7;
            const __nv_bfloat16* src = (bufl ? Bl : Bh) + (size_t)row * 512 + c * 64 + ch * 8;
            uint32_t cb = (uint32_t)(ch * 16) ^ (((uint32_t)row & 7u) << 4);
            *(uint4*)(sm + 32768 + bufl * 8192 + row * 128 + cb) = *(const uint4*)src;
        }
        __syncthreads();

#pragma unroll
        for (int s = 0; s < 4; s++) {
            uint32_t ah[2][4], al[2][4], bh[2][4], bl[2][4];
#pragma unroll
            for (int msub = 0; msub < 2; msub++) {
                uint32_t row = (uint32_t)(wm * 32 + msub * 16 + ((t8 & 1) << 3) + lr);
                uint32_t cb  = ((uint32_t)s << 5) + (((uint32_t)t8 >> 1) << 4);
                uint32_t a = sbase + sw128b(row, cb);
                ldsm_x4(ah[msub], a);
                ldsm_x4(al[msub], a + 16384);
            }
#pragma unroll
            for (int nsub = 0; nsub < 2; nsub++) {
                uint32_t row = (uint32_t)(wn * 32 + nsub * 16 + ((t8 >> 1) << 3) + lr);
                uint32_t cb  = ((uint32_t)s << 5) + (((uint32_t)t8 & 1u) << 4);
                uint32_t a = sbase + 32768 + sw128b(row, cb);
                ldsm_x4(bh[nsub], a);
                ldsm_x4(bl[nsub], a + 8192);
            }
#pragma unroll
            for (int msub = 0; msub < 2; msub++)
#pragma unroll
                for (int n8 = 0; n8 < 4; n8++) {
                    const uint32_t* bhp = &bh[n8 >> 1][(n8 & 1) * 2];
                    const uint32_t* blp = &bl[n8 >> 1][(n8 & 1) * 2];
                    mma16816(acc[msub][n8], ah[msub], bhp);
                    mma16816(acc[msub][n8], ah[msub], blp);
                    mma16816(acc[msub][n8], al[msub], bhp);
                }
        }
        __syncthreads();
    }

    float* ep = (float*)sm;
    int g = lane >> 2, tq = lane & 3;
#pragma unroll
    for (int msub = 0; msub < 2; msub++)
#pragma unroll
        for (int n8 = 0; n8 < 4; n8++)
#pragma unroll
            for (int i = 0; i < 4; i++) {
                int row = wm * 32 + msub * 16 + ((i >> 1) << 3) + g;
                int col = wn * 32 + n8 * 8 + tq * 2 + (i & 1);
                ep[row * 65 + col] = acc[msub][n8][i];
            }
    __syncthreads();
    int mr = tid >> 4, kq = tid & 15;
    float4 bb = make_float4(0.f, 0.f, 0.f, 0.f);
    if (bias) bb = *(const float4*)&bias[kq * 4];
#pragma unroll
    for (int it = 0; it < 8; it++) {
        int m = it * 16 + mr;
        float4 o;
        o.x = ep[m * 65 + kq * 4 + 0] + bb.x;
        o.y = ep[m * 65 + kq * 4 + 1] + bb.y;
        o.z = ep[m * 65 + kq * 4 + 2] + bb.z;
        o.w = ep[m * 65 + kq * 4 + 3] + bb.w;
        if (relu) {
            o.x = fmaxf(o.x, 0.f); o.y = fmaxf(o.y, 0.f);
            o.z = fmaxf(o.z, 0.f); o.w = fmaxf(o.w, 0.f);
        }
        *(float4*)(C + (size_t)(m0 + m) * ldc + kq * 4) = o;
    }
}

__global__ __launch_bounds__(256) void k_mm_nt(int aslot, unsigned boff, int cslot,
                                               const float* __restrict__ bias, int relu)
{
    const float* A = g_arena + (size_t)aslot * SLOT;
    float* C = g_arena + (size_t)cslot * SLOT;
    int n0 = blockIdx.y * 64;
    mm_tile(A, g_wbf_hi + boff + (size_t)n0 * 512, g_wbf_lo + boff + (size_t)n0 * 512,
            C + n0, 512, bias ? bias + n0 : nullptr, relu, blockIdx.x * 128);
}

// ===========================================================================
// Prep kernels
// ===========================================================================
__device__ __forceinline__ void wsplit(size_t o, float v) {
    __nv_bfloat16 h = __float2bfloat16_rn(v);
    g_wbf_hi[o] = h;
    g_wbf_lo[o] = __float2bfloat16_rn(v - __bfloat162float(h));
}
__global__ __launch_bounds__(256) void k_prep_qkv(const float* __restrict__ Wq,
    const float* __restrict__ Wk, const float* __restrict__ Wv)
{
    int z = blockIdx.y, which = z >> 3, h = z & 7;
    const float* W = (which == 0 ? Wq : (which == 1 ? Wk : Wv)) + (size_t)h * 32768;
    int i = blockIdx.x * 256 + threadIdx.x;
    int dk = i >> 9, dd = i & 511;
    wsplit((size_t)WOFF_QKV + (size_t)z * 32768 + i, W[dd * 64 + dk]);
}
__global__ __launch_bounds__(256) void k_prep_wo(const float* __restrict__ Wo)
{
    int i = blockIdx.x * 256 + threadIdx.x;
    int dd = i >> 9, hdk = i & 511;
    wsplit((size_t)WOFF_WO + i, Wo[hdk * 512 + dd]);
}
__global__ __launch_bounds__(256) void k_prep_ff(const float* __restrict__ w1,
                                                 const float* __restrict__ w2)
{
    int i = blockIdx.x * 256 + threadIdx.x;
    float v = (i < 262144) ? w1[i] : w2[i - 262144];
    wsplit((size_t)WOFF_FF1 + i, v);
}
__global__ __launch_bounds__(256) void k_prep_x(const float* __restrict__ x)
{
    size_t i = (size_t)blockIdx.x * 256 + threadIdx.x;   // 16777216
    float v = x[i];
    __nv_bfloat16 h = __float2bfloat16_rn(v);
    g_xh[i] = h;
    g_xl[i] = __float2bfloat16_rn(v - __bfloat162float(h));
}

// ===========================================================================
// Deterministic two-stage BatchNorm (unchanged)
// ===========================================================================
__global__ __launch_bounds__(256) void k_bnstats(int aslot, int bslot, float scale)
{
    const float* A = g_arena + (size_t)aslot * SLOT;
    const float* Bopt = (bslot >= 0) ? (g_arena + (size_t)bslot * SLOT) : nullptr;
    int c = blockIdx.x * 256 + threadIdx.x;
    int chunk = blockIdx.y;
    int r0 = chunk * 128;
    float s = 0.f, q = 0.f;
    for (int r = r0; r < r0 + 128; r++) {
        float t = A[(size_t)r * 512 + c];
        if (Bopt) t += Bopt[(size_t)r * 512 + c];
        t *= scale;
        s += t; q += t * t;
    }
    g_psum[chunk * 512 + c] = s;
    g_psq[chunk * 512 + c]  = q;
}

__global__ __launch_bounds__(512) void k_bnfinal(const float* __restrict__ w,
                                                 const float* __restrict__ bias)
{
    int c = threadIdx.x;
    float s = 0.f, q = 0.f;
    for (int i = 0; i < 256; i++) { s += g_psum[i * 512 + c]; q += g_psq[i * 512 + c]; }
    float m   = s * (1.f / 32768.f);
    float var = q * (1.f / 32768.f) - m * m;
    float inv = rsqrtf(var + 1e-5f);
    float g   = inv * w[c];
    g_gamma[c] = g;
    g_beta[c]  = bias[c] - m * g;
}

__global__ __launch_bounds__(256) void k_bnapply(int aslot, int bslot, float scale,
                                                 int outslot, float* __restrict__ ext_out)
{
    const float* A = g_arena + (size_t)aslot * SLOT;
    const float* Bopt = (bslot >= 0) ? (g_arena + (size_t)bslot * SLOT) : nullptr;
    float* out = (outslot >= 0) ? (g_arena + (size_t)outslot * SLOT) : ext_out;
    size_t i = ((size_t)blockIdx.x * 256 + threadIdx.x) * 4;
    int c = (int)(i & 511);
    float4 a = *(const float4*)(A + i);
    if (Bopt) {
        float4 b = *(const float4*)(Bopt + i);
        a.x += b.x; a.y += b.y; a.z += b.z; a.w += b.w;
    }
    float4 g = *(const float4*)&g_gamma[c];
    float4 bt = *(const float4*)&g_beta[c];
    float4 y;
    y.x = scale * a.x * g.x + bt.x;
    y.y = scale * a.y * g.y + bt.y;
    y.z = scale * a.z * g.z + bt.z;
    y.w = scale * a.w * g.w + bt.w;
    *(float4*)(out + i) = y;
}

// ===========================================================================
// Pipeline (kernel launches only)
// ===========================================================================
extern "C" void kernel_launch(void* const* d_in, const int* in_sizes, int n_in,
                              void* d_out, int out_size)
{
    const float* x    = (const float*)d_in[0];
    const float* Wq   = (const float*)d_in[1];
    const float* Wk   = (const float*)d_in[2];
    const float* Wv   = (const float*)d_in[3];
    const float* Wo   = (const float*)d_in[4];
    const float* n1w  = (const float*)d_in[5];
    const float* n1b  = (const float*)d_in[6];
    const float* n2w  = (const float*)d_in[7];
    const float* n2b  = (const float*)d_in[8];
    const float* ffw1 = (const float*)d_in[9];
    const float* ffb1 = (const float*)d_in[10];
    const float* ffw2 = (const float*)d_in[11];
    const float* ffb2 = (const float*)d_in[12];

    // 0. prep: weights + x split
    k_prep_qkv<<<dim3(128, 24), 256>>>(Wq, Wk, Wv);
    k_prep_wo<<<1024, 256>>>(Wo);
    k_prep_ff<<<2048, 256>>>(ffw1, ffw2);
    k_prep_x<<<65536, 256>>>(x);

    // 1. fused QKV -> bf16 Q/K/Vt
    k_mm_qkv3<<<dim3(256, 8), 256>>>();

    // 2. HMMA flash attention -> heads slot3
    k_attn_mma<<<dim3(4, 64, 8), 256>>>();

    // 3. output projection -> slot4
    k_mm_nt<<<dim3(256, 8), 256>>>(3, WOFF_WO, 4, nullptr, 0);

    // 4. BN1 on 2*proj -> slot0 (h)
    k_bnstats<<<dim3(2, 256), 256>>>(4, -1, 2.f);
    k_bnfinal<<<1, 512>>>(n1w, n1b);
    k_bnapply<<<16384, 256>>>(4, -1, 2.f, 0, nullptr);

    // 5. FFN
    k_mm_nt<<<dim3(256, 8), 256>>>(0, WOFF_FF1, 1, ffb1, 1);
    k_mm_nt<<<dim3(256, 8), 256>>>(1, WOFF_FF2, 2, ffb2, 0);

    // 6. BN2 on 2*(h + ff2) -> d_out
    k_bnstats<<<dim3(2, 256), 256>>>(0, 2, 2.f);
    k_bnfinal<<<1, 512>>>(n2w, n2b);
    k_bnapply<<<16384, 256>>>(0, 2, 2.f, -1, (float*)d_out);
}

// round 9
// speedup vs baseline: 2.8293x; 1.1676x over previous
#include <cuda_runtime.h>
#include <cuda_bf16.h>
#include <math.h>
#include <stdint.h>

#define B_BATCH 64
#define N_SEQ   512
#define D_MOD   512
#define H_HEADS 8
#define DK_HEAD 64
#define BN_TOT  32768
#define SLOT    16777216u

// fp32 arena: slot0 = proj, slot1 = ff2
__device__ float g_arena[2u * SLOT];
__device__ float g_psum[256 * 512];
__device__ float g_psq[256 * 512];
__device__ float g_gamma[512];
__device__ float g_beta[512];

#define WOFF_QKV 0u
#define WOFF_WO  786432u
#define WOFF_FF1 1048576u
#define WOFF_FF2 1310720u
__device__ __align__(128) __nv_bfloat16 g_wbf_hi[1572864];
__device__ __align__(128) __nv_bfloat16 g_wbf_lo[1572864];

// bf16 hi/lo activation streams [m][512] (Vt: [h][b][dv][512])
__device__ __align__(128) __nv_bfloat16 g_xh[16777216],  g_xl[16777216];
__device__ __align__(128) __nv_bfloat16 g_qh[16777216],  g_ql[16777216];
__device__ __align__(128) __nv_bfloat16 g_kh[16777216],  g_kl[16777216];
__device__ __align__(128) __nv_bfloat16 g_vth[16777216], g_vtl[16777216];
__device__ __align__(128) __nv_bfloat16 g_hdh[16777216], g_hdl[16777216];  // heads
__device__ __align__(128) __nv_bfloat16 g_hh[16777216],  g_hl[16777216];   // post-BN1 h
__device__ __align__(128) __nv_bfloat16 g_f1h[16777216], g_f1l[16777216];  // ff1

// ===========================================================================
// Helpers
// ===========================================================================
__device__ __forceinline__ uint32_t smem_u32(const void* p) {
    uint32_t a;
    asm("{ .reg .u64 t; cvta.to.shared.u64 t, %1; cvt.u32.u64 %0, t; }" : "=r"(a) : "l"(p));
    return a;
}
__device__ __forceinline__ void ldsm_x4(uint32_t* r, uint32_t addr) {
    asm volatile("ldmatrix.sync.aligned.m8n8.x4.shared.b16 {%0,%1,%2,%3}, [%4];"
        : "=r"(r[0]), "=r"(r[1]), "=r"(r[2]), "=r"(r[3]) : "r"(addr));
}
__device__ __forceinline__ void mma16816(float* c, const uint32_t* a, const uint32_t* b) {
    asm volatile("mma.sync.aligned.m16n8k16.row.col.f32.bf16.bf16.f32 "
        "{%0,%1,%2,%3}, {%4,%5,%6,%7}, {%8,%9}, {%0,%1,%2,%3};"
        : "+f"(c[0]), "+f"(c[1]), "+f"(c[2]), "+f"(c[3])
        : "r"(a[0]), "r"(a[1]), "r"(a[2]), "r"(a[3]), "r"(b[0]), "r"(b[1]));
}
__device__ __forceinline__ uint32_t pack2(__nv_bfloat16 a, __nv_bfloat16 b) {
    return (uint32_t)__bfloat16_as_ushort(a) | ((uint32_t)__bfloat16_as_ushort(b) << 16);
}
__device__ __forceinline__ __nv_bfloat16 bhi(float v) { return __float2bfloat16_rn(v); }
__device__ __forceinline__ __nv_bfloat16 blo(float v, __nv_bfloat16 h) {
    return __float2bfloat16_rn(v - __bfloat162float(h));
}
__device__ __forceinline__ uint32_t sw128b(uint32_t row, uint32_t cb) {
    return row * 128 + (cb ^ ((row & 7u) << 4));
}
__device__ __forceinline__ uint32_t sw32b(uint32_t row, uint32_t cb) {
    return (row >> 1) * 128 + ((((row & 1u) << 6) | cb) ^ (((row >> 1) & 7u) << 4));
}
#define CP16(dst, src) \
    asm volatile("cp.async.cg.shared.global [%0], [%1], 16;" :: "r"(dst), "l"(src) : "memory")
#define CP_COMMIT() asm volatile("cp.async.commit_group;" ::: "memory")
#define CP_WAIT0()  asm volatile("cp.async.wait_group 0;" ::: "memory")
#define CP_WAIT1()  asm volatile("cp.async.wait_group 1;" ::: "memory")

extern __shared__ char dynsm[];

// ===========================================================================
// Fused QKV (cp.async double-buffered). Block = (m-tile 128, head h).
// Buffer (40960B): Ah@0 Al@8192 B@16384+which*8192+hl*4096. 2 buffers.
// ===========================================================================
#define QKV_SMEM 81920
__global__ __launch_bounds__(256) void k_mm_qkv3()
{
    const uint32_t sb = smem_u32(dynsm);
    const int h = blockIdx.y;
    const int m0 = blockIdx.x * 128;
    const int tid = threadIdx.x, lane = tid & 31, wid = tid >> 5;
    const int wm = wid >> 1, wn = wid & 1;
    const int t8 = lane >> 3, lr = lane & 7;

    auto stage = [&](int c, uint32_t bufb) {
#pragma unroll
        for (int it = 0; it < 4; it++) {
            int idx = it * 256 + tid;
            int arr = idx >> 9, rem = idx & 511;
            int row = rem >> 2, f8 = rem & 3;
            const __nv_bfloat16* src = (arr ? g_xl : g_xh)
                + (size_t)(m0 + row) * 512 + c * 32 + f8 * 8;
            CP16(bufb + arr * 8192 + sw32b(row, f8 * 16), src);
        }
#pragma unroll
        for (int it = 0; it < 6; it++) {
            int idx = it * 256 + tid;
            int which = idx >> 9, rem = idx & 511;
            int hl = rem >> 8, r2 = rem & 255;
            int row = r2 >> 2, f8 = r2 & 3;
            const __nv_bfloat16* src = (hl ? g_wbf_lo : g_wbf_hi)
                + (size_t)(which * 8 + h) * 32768 + (size_t)row * 512 + c * 32 + f8 * 8;
            CP16(bufb + 16384 + which * 8192 + hl * 4096 + sw32b(row, f8 * 16), src);
        }
        CP_COMMIT();
    };

    float acc[3][2][4][4];
#pragma unroll
    for (int q = 0; q < 3; q++)
#pragma unroll
        for (int i = 0; i < 2; i++)
#pragma unroll
            for (int j = 0; j < 4; j++)
#pragma unroll
                for (int k = 0; k < 4; k++) acc[q][i][j][k] = 0.f;

    stage(0, sb);
    stage(1, sb + 40960);

    for (int c = 0; c < 16; c++) {
        if (c == 15) CP_WAIT0(); else CP_WAIT1();
        __syncthreads();
        const uint32_t bufb = sb + (uint32_t)(c & 1) * 40960;
#pragma unroll
        for (int s = 0; s < 2; s++) {
            uint32_t ah[2][4], al[2][4];
#pragma unroll
            for (int msub = 0; msub < 2; msub++) {
                uint32_t row = (uint32_t)(wm * 32 + msub * 16 + ((t8 & 1) << 3) + lr);
                uint32_t cb  = ((uint32_t)s << 5) + (((uint32_t)t8 >> 1) << 4);
                uint32_t off = sw32b(row, cb);
                ldsm_x4(ah[msub], bufb + off);
                ldsm_x4(al[msub], bufb + 8192 + off);
            }
#pragma unroll
            for (int q = 0; q < 3; q++) {
                uint32_t bh[2][4], bl[2][4];
#pragma unroll
                for (int nsub = 0; nsub < 2; nsub++) {
                    uint32_t row = (uint32_t)(wn * 32 + nsub * 16 + ((t8 >> 1) << 3) + lr);
                    uint32_t cb  = ((uint32_t)s << 5) + (((uint32_t)t8 & 1u) << 4);
                    uint32_t off = sw32b(row, cb);
                    ldsm_x4(bh[nsub], bufb + 16384 + q * 8192 + off);
                    ldsm_x4(bl[nsub], bufb + 16384 + q * 8192 + 4096 + off);
                }
#pragma unroll
                for (int msub = 0; msub < 2; msub++)
#pragma unroll
                    for (int n8 = 0; n8 < 4; n8++) {
                        const uint32_t* bhp = &bh[n8 >> 1][(n8 & 1) * 2];
                        const uint32_t* blp = &bl[n8 >> 1][(n8 & 1) * 2];
                        mma16816(acc[q][msub][n8], ah[msub], bhp);
                        mma16816(acc[q][msub][n8], ah[msub], blp);
                        mma16816(acc[q][msub][n8], al[msub], bhp);
                    }
            }
        }
        __syncthreads();
        if (c + 2 < 16) stage(c + 2, sb + (uint32_t)(c & 1) * 40960);
    }

    // epilogue: per which, acc -> ep smem -> bf16 hi/lo global
    float* ep = (float*)dynsm;                  // 128 x 65 fp32
    const int g = lane >> 2, tq = lane & 3;
    const int b = m0 >> 9, n0 = m0 & 511;
    const size_t vtoff = (size_t)(h * 64 + b) * 32768;

#pragma unroll
    for (int q = 0; q < 3; q++) {
        __syncthreads();
#pragma unroll
        for (int msub = 0; msub < 2; msub++)
#pragma unroll
            for (int n8 = 0; n8 < 4; n8++)
#pragma unroll
                for (int i = 0; i < 4; i++) {
                    int row = wm * 32 + msub * 16 + ((i >> 1) << 3) + g;
                    int col = wn * 32 + n8 * 8 + tq * 2 + (i & 1);
                    ep[row * 65 + col] = acc[q][msub][n8][i];
                }
        __syncthreads();
        if (q < 2) {
            __nv_bfloat16* Dh = q ? g_kh : g_qh;
            __nv_bfloat16* Dl = q ? g_kl : g_ql;
            int mr = tid >> 4, kq = tid & 15;
#pragma unroll
            for (int it = 0; it < 8; it++) {
                int m = it * 16 + mr;
                float fx = ep[m * 65 + kq * 4 + 0];
                float fy = ep[m * 65 + kq * 4 + 1];
                float fz = ep[m * 65 + kq * 4 + 2];
                float fw = ep[m * 65 + kq * 4 + 3];
                __nv_bfloat16 h0 = bhi(fx), h1 = bhi(fy), h2 = bhi(fz), h3 = bhi(fw);
                uint2 hv = make_uint2(pack2(h0, h1), pack2(h2, h3));
                uint2 lv = make_uint2(pack2(blo(fx, h0), blo(fy, h1)),
                                      pack2(blo(fz, h2), blo(fw, h3)));
                size_t o = ((size_t)h * BN_TOT + (size_t)(m0 + m)) * 64 + kq * 4;
                *(uint2*)(Dh + o) = hv;
                *(uint2*)(Dl + o) = lv;
            }
        } else {
            int nn = (tid & 15) * 8;
#pragma unroll
            for (int p = 0; p < 4; p++) {
                int dv = p * 16 + (tid >> 4);
                __nv_bfloat16 hs[8], ls[8];
#pragma unroll
                for (int j = 0; j < 8; j++) {
                    float v = ep[(nn + j) * 65 + dv];
                    hs[j] = bhi(v);
                    ls[j] = blo(v, hs[j]);
                }
                size_t o = vtoff + (size_t)dv * 512 + n0 + nn;
                *(uint4*)(g_vth + o) = make_uint4(pack2(hs[0], hs[1]), pack2(hs[2], hs[3]),
                                                  pack2(hs[4], hs[5]), pack2(hs[6], hs[7]));
                *(uint4*)(g_vtl + o) = make_uint4(pack2(ls[0], ls[1]), pack2(ls[2], ls[3]),
                                                  pack2(ls[4], ls[5]), pack2(ls[6], ls[7]));
            }
        }
    }
}

// ===========================================================================
// HMMA flash attention, cp.async double-buffered K/V.
// Dynamic smem: Qh@0 Ql@16384, KV buffers @32768 + (kt&1)*32768
//   (Kh@+0, Kl@+8192, Vth@+16384, Vtl@+24576). Total 98304.
// Heads written as bf16 hi/lo.
// ===========================================================================
#define ATTN_SMEM 98304
__global__ __launch_bounds__(256) void k_attn_mma()
{
    const uint32_t sb = smem_u32(dynsm);
    const int h = blockIdx.z, b = blockIdx.y, q0 = blockIdx.x * 128;
    const int tid = threadIdx.x, lane = tid & 31, w = tid >> 5;
    const int t8 = lane >> 3, lr = lane & 7;

    const size_t qbase = ((size_t)h * BN_TOT + (size_t)b * 512 + q0) * 64;
    const size_t kbase = ((size_t)h * BN_TOT + (size_t)b * 512) * 64;
    const size_t vtoff = (size_t)(h * 64 + b) * 32768;

    auto stage_kv = [&](int kt, uint32_t bufb) {
#pragma unroll
        for (int it = 0; it < 8; it++) {
            int idx = it * 256 + tid;
            int arr = idx >> 9, rem = idx & 511;
            int row = rem >> 3, f8 = rem & 7;
            const __nv_bfloat16* src;
            if (arr == 0)      src = g_kh  + kbase + (size_t)(kt * 64 + row) * 64 + f8 * 8;
            else if (arr == 1) src = g_kl  + kbase + (size_t)(kt * 64 + row) * 64 + f8 * 8;
            else if (arr == 2) src = g_vth + vtoff + (size_t)row * 512 + kt * 64 + f8 * 8;
            else               src = g_vtl + vtoff + (size_t)row * 512 + kt * 64 + f8 * 8;
            CP16(bufb + arr * 8192 + sw128b(row, f8 * 16), src);
        }
        CP_COMMIT();
    };

    // stage Q (regular stores)
#pragma unroll
    for (int it = 0; it < 8; it++) {
        int idx = it * 256 + tid;
        int arr = idx >> 10, rem = idx & 1023;
        int row = rem >> 3, f8 = rem & 7;
        const __nv_bfloat16* src = (arr ? g_ql : g_qh) + qbase + (size_t)row * 64 + f8 * 8;
        *(uint4*)(dynsm + arr * 16384 + sw128b(row, f8 * 16)) = *(const uint4*)src;
    }
    stage_kv(0, sb + 32768);
    stage_kv(1, sb + 65536);
    __syncthreads();

    uint32_t qh[4][4], ql[4][4];
#pragma unroll
    for (int s = 0; s < 4; s++) {
        uint32_t row = (uint32_t)(w * 16 + ((t8 & 1) << 3) + lr);
        uint32_t cb  = ((uint32_t)s << 5) + (((uint32_t)t8 >> 1) << 4);
        uint32_t off = sw128b(row, cb);
        ldsm_x4(qh[s], sb + off);
        ldsm_x4(ql[s], sb + 16384 + off);
    }

    float o[8][4];
#pragma unroll
    for (int n8 = 0; n8 < 8; n8++)
#pragma unroll
        for (int i = 0; i < 4; i++) o[n8][i] = 0.f;
    float m0_ = -1e30f, m1_ = -1e30f, l0 = 0.f, l1 = 0.f;

    for (int kt = 0; kt < 8; kt++) {
        if (kt == 7) CP_WAIT0(); else CP_WAIT1();
        __syncthreads();
        const uint32_t kvb = sb + 32768 + (uint32_t)(kt & 1) * 32768;

        float s[8][4];
#pragma unroll
        for (int n8 = 0; n8 < 8; n8++)
#pragma unroll
            for (int i = 0; i < 4; i++) s[n8][i] = 0.f;
#pragma unroll
        for (int ks = 0; ks < 4; ks++) {
            uint32_t bh[4][4], bl[4][4];
#pragma unroll
            for (int nsub = 0; nsub < 4; nsub++) {
                uint32_t row = (uint32_t)(nsub * 16 + ((t8 >> 1) << 3) + lr);
                uint32_t cb  = ((uint32_t)ks << 5) + (((uint32_t)t8 & 1u) << 4);
                uint32_t off = sw128b(row, cb);
                ldsm_x4(bh[nsub], kvb + off);
                ldsm_x4(bl[nsub], kvb + 8192 + off);
            }
#pragma unroll
            for (int n8 = 0; n8 < 8; n8++) {
                const uint32_t* bhp = &bh[n8 >> 1][(n8 & 1) * 2];
                const uint32_t* blp = &bl[n8 >> 1][(n8 & 1) * 2];
                mma16816(s[n8], qh[ks], bhp);
                mma16816(s[n8], qh[ks], blp);
                mma16816(s[n8], ql[ks], bhp);
            }
        }

        // online softmax
        float mx0 = -1e30f, mx1 = -1e30f;
#pragma unroll
        for (int n8 = 0; n8 < 8; n8++) {
            s[n8][0] *= 0.125f; s[n8][1] *= 0.125f; s[n8][2] *= 0.125f; s[n8][3] *= 0.125f;
            mx0 = fmaxf(mx0, fmaxf(s[n8][0], s[n8][1]));
            mx1 = fmaxf(mx1, fmaxf(s[n8][2], s[n8][3]));
        }
        mx0 = fmaxf(mx0, __shfl_xor_sync(0xffffffffu, mx0, 1));
        mx0 = fmaxf(mx0, __shfl_xor_sync(0xffffffffu, mx0, 2));
        mx1 = fmaxf(mx1, __shfl_xor_sync(0xffffffffu, mx1, 1));
        mx1 = fmaxf(mx1, __shfl_xor_sync(0xffffffffu, mx1, 2));
        float mn0 = fmaxf(m0_, mx0), mn1 = fmaxf(m1_, mx1);
        float a0 = __expf(m0_ - mn0), a1 = __expf(m1_ - mn1);
        m0_ = mn0; m1_ = mn1;
        float rs0 = 0.f, rs1 = 0.f;
#pragma unroll
        for (int n8 = 0; n8 < 8; n8++) {
            s[n8][0] = __expf(s[n8][0] - mn0); s[n8][1] = __expf(s[n8][1] - mn0);
            s[n8][2] = __expf(s[n8][2] - mn1); s[n8][3] = __expf(s[n8][3] - mn1);
            rs0 += s[n8][0] + s[n8][1];
            rs1 += s[n8][2] + s[n8][3];
        }
        rs0 += __shfl_xor_sync(0xffffffffu, rs0, 1);
        rs0 += __shfl_xor_sync(0xffffffffu, rs0, 2);
        rs1 += __shfl_xor_sync(0xffffffffu, rs1, 1);
        rs1 += __shfl_xor_sync(0xffffffffu, rs1, 2);
        l0 = l0 * a0 + rs0;
        l1 = l1 * a1 + rs1;
#pragma unroll
        for (int n8 = 0; n8 < 8; n8++) {
            o[n8][0] *= a0; o[n8][1] *= a0; o[n8][2] *= a1; o[n8][3] *= a1;
        }

        uint32_t ph[4][4], pl[4][4];
#pragma unroll
        for (int ks = 0; ks < 4; ks++) {
            int na = 2 * ks, nb = 2 * ks + 1;
            __nv_bfloat16 h0 = bhi(s[na][0]), h1 = bhi(s[na][1]),
                          h2 = bhi(s[na][2]), h3 = bhi(s[na][3]);
            __nv_bfloat16 h4 = bhi(s[nb][0]), h5 = bhi(s[nb][1]),
                          h6 = bhi(s[nb][2]), h7 = bhi(s[nb][3]);
            ph[ks][0] = pack2(h0, h1); ph[ks][1] = pack2(h2, h3);
            ph[ks][2] = pack2(h4, h5); ph[ks][3] = pack2(h6, h7);
            pl[ks][0] = pack2(blo(s[na][0], h0), blo(s[na][1], h1));
            pl[ks][1] = pack2(blo(s[na][2], h2), blo(s[na][3], h3));
            pl[ks][2] = pack2(blo(s[nb][0], h4), blo(s[nb][1], h5));
            pl[ks][3] = pack2(blo(s[nb][2], h6), blo(s[nb][3], h7));
        }

#pragma unroll
        for (int ks = 0; ks < 4; ks++) {
            uint32_t vh[4][4], vl[4][4];
#pragma unroll
            for (int nsub = 0; nsub < 4; nsub++) {
                uint32_t row = (uint32_t)(nsub * 16 + ((t8 >> 1) << 3) + lr);
                uint32_t cb  = ((uint32_t)ks << 5) + (((uint32_t)t8 & 1u) << 4);
                uint32_t off = sw128b(row, cb);
                ldsm_x4(vh[nsub], kvb + 16384 + off);
                ldsm_x4(vl[nsub], kvb + 24576 + off);
            }
#pragma unroll
            for (int n8 = 0; n8 < 8; n8++) {
                const uint32_t* vhp = &vh[n8 >> 1][(n8 & 1) * 2];
                const uint32_t* vlp = &vl[n8 >> 1][(n8 & 1) * 2];
                mma16816(o[n8], ph[ks], vhp);
                mma16816(o[n8], ph[ks], vlp);
                mma16816(o[n8], pl[ks], vhp);
            }
        }
        __syncthreads();
        if (kt + 2 < 8) stage_kv(kt + 2, sb + 32768 + (uint32_t)(kt & 1) * 32768);
    }

    // epilogue: normalize, heads -> bf16 hi/lo
    float inv0 = 1.f / l0, inv1 = 1.f / l1;
    float* ep = (float*)dynsm;
    int r0 = lane >> 2, c2 = (lane & 3) * 2;
#pragma unroll
    for (int n8 = 0; n8 < 8; n8++) {
        ep[(w * 16 + r0) * 65 + n8 * 8 + c2]     = o[n8][0] * inv0;
        ep[(w * 16 + r0) * 65 + n8 * 8 + c2 + 1] = o[n8][1] * inv0;
        ep[(w * 16 + r0 + 8) * 65 + n8 * 8 + c2]     = o[n8][2] * inv1;
        ep[(w * 16 + r0 + 8) * 65 + n8 * 8 + c2 + 1] = o[n8][3] * inv1;
    }
    __syncthreads();
    int mr = tid >> 4, kq = tid & 15;
#pragma unroll
    for (int it = 0; it < 8; it++) {
        int m = it * 16 + mr;
        float fx = ep[m * 65 + kq * 4 + 0];
        float fy = ep[m * 65 + kq * 4 + 1];
        float fz = ep[m * 65 + kq * 4 + 2];
        float fw = ep[m * 65 + kq * 4 + 3];
        __nv_bfloat16 h0 = bhi(fx), h1 = bhi(fy), h2 = bhi(fz), h3 = bhi(fw);
        size_t row = (size_t)b * 512 + q0 + m;
        size_t oo = row * 512 + h * 64 + kq * 4;
        *(uint2*)(g_hdh + oo) = make_uint2(pack2(h0, h1), pack2(h2, h3));
        *(uint2*)(g_hdl + oo) = make_uint2(pack2(blo(fx, h0), blo(fy, h1)),
                                           pack2(blo(fz, h2), blo(fw, h3)));
    }
}

// ===========================================================================
// Unified bf16-in GEMM: C[128x64 tile] = (Ah+Al)[m][512] @ (Bh+Bl)[n][512]^T
// cp.async double-buffered, BK=32. which: 0=proj 1=ff1 2=ff2.
// Buffer (24576B): Ah@0 Al@8192 Bh@16384 Bl@20480. Static 48KB.
// ===========================================================================
__global__ __launch_bounds__(256) void k_mm_bf(int which, const float* __restrict__ bias)
{
    __shared__ __align__(1024) char sm[49152];
    const uint32_t sb = smem_u32(sm);
    const int tid = threadIdx.x, lane = tid & 31, wid = tid >> 5;
    const int wm = wid >> 1, wn = wid & 1;
    const int t8 = lane >> 3, lr = lane & 7;
    const int m0 = blockIdx.x * 128, n0 = blockIdx.y * 64;

    const __nv_bfloat16 *Ah, *Al;
    unsigned boff;
    float* Cf = nullptr;
    __nv_bfloat16 *Ch = nullptr, *Cl = nullptr;
    int relu = 0;
    if (which == 0)      { Ah = g_hdh; Al = g_hdl; boff = WOFF_WO;  Cf = g_arena; }
    else if (which == 1) { Ah = g_hh;  Al = g_hl;  boff = WOFF_FF1; Ch = g_f1h; Cl = g_f1l; relu = 1; }
    else                 { Ah = g_f1h; Al = g_f1l; boff = WOFF_FF2; Cf = g_arena + SLOT; }

    auto stage = [&](int c, uint32_t bufb) {
#pragma unroll
        for (int it = 0; it < 4; it++) {
            int idx = it * 256 + tid;
            int arr = idx >> 9, rem = idx & 511;
            int row = rem >> 2, f8 = rem & 3;
            const __nv_bfloat16* src = (arr ? Al : Ah)
                + (size_t)(m0 + row) * 512 + c * 32 + f8 * 8;
            CP16(bufb + arr * 8192 + sw32b(row, f8 * 16), src);
        }
#pragma unroll
        for (int it = 0; it < 2; it++) {
            int idx = it * 256 + tid;
            int hl = idx >> 8, rem = idx & 255;
            int row = rem >> 2, f8 = rem & 3;
            const __nv_bfloat16* src = (hl ? g_wbf_lo : g_wbf_hi)
                + boff + (size_t)(n0 + row) * 512 + c * 32 + f8 * 8;
            CP16(bufb + 16384 + hl * 4096 + sw32b(row, f8 * 16), src);
        }
        CP_COMMIT();
    };

    float acc[2][4][4];
#pragma unroll
    for (int i = 0; i < 2; i++)
#pragma unroll
        for (int j = 0; j < 4; j++)
#pragma unroll
            for (int k = 0; k < 4; k++) acc[i][j][k] = 0.f;

    stage(0, sb);
    stage(1, sb + 24576);

    for (int c = 0; c < 16; c++) {
        if (c == 15) CP_WAIT0(); else CP_WAIT1();
        __syncthreads();
        const uint32_t bufb = sb + (uint32_t)(c & 1) * 24576;
#pragma unroll
        for (int s = 0; s < 2; s++) {
            uint32_t ah[2][4], al[2][4], bh[2][4], bl[2][4];
#pragma unroll
            for (int msub = 0; msub < 2; msub++) {
                uint32_t row = (uint32_t)(wm * 32 + msub * 16 + ((t8 & 1) << 3) + lr);
                uint32_t cb  = ((uint32_t)s << 5) + (((uint32_t)t8 >> 1) << 4);
                uint32_t off = sw32b(row, cb);
                ldsm_x4(ah[msub], bufb + off);
                ldsm_x4(al[msub], bufb + 8192 + off);
            }
#pragma unroll
            for (int nsub = 0; nsub < 2; nsub++) {
                uint32_t row = (uint32_t)(wn * 32 + nsub * 16 + ((t8 >> 1) << 3) + lr);
                uint32_t cb  = ((uint32_t)s << 5) + (((uint32_t)t8 & 1u) << 4);
                uint32_t off = sw32b(row, cb);
                ldsm_x4(bh[nsub], bufb + 16384 + off);
                ldsm_x4(bl[nsub], bufb + 20480 + off);
            }
#pragma unroll
            for (int msub = 0; msub < 2; msub++)
#pragma unroll
                for (int n8 = 0; n8 < 4; n8++) {
                    const uint32_t* bhp = &bh[n8 >> 1][(n8 & 1) * 2];
                    const uint32_t* blp = &bl[n8 >> 1][(n8 & 1) * 2];
                    mma16816(acc[msub][n8], ah[msub], bhp);
                    mma16816(acc[msub][n8], ah[msub], blp);
                    mma16816(acc[msub][n8], al[msub], bhp);
                }
        }
        __syncthreads();
        if (c + 2 < 16) stage(c + 2, sb + (uint32_t)(c & 1) * 24576);
    }

    float* ep = (float*)sm;
    int g = lane >> 2, tq = lane & 3;
#pragma unroll
    for (int msub = 0; msub < 2; msub++)
#pragma unroll
        for (int n8 = 0; n8 < 4; n8++)
#pragma unroll
            for (int i = 0; i < 4; i++) {
                int row = wm * 32 + msub * 16 + ((i >> 1) << 3) + g;
                int col = wn * 32 + n8 * 8 + tq * 2 + (i & 1);
                ep[row * 65 + col] = acc[msub][n8][i];
            }
    __syncthreads();
    int mr = tid >> 4, kq = tid & 15;
    float4 bb = make_float4(0.f, 0.f, 0.f, 0.f);
    if (bias) bb = *(const float4*)&bias[n0 + kq * 4];
#pragma unroll
    for (int it = 0; it < 8; it++) {
        int m = it * 16 + mr;
        float fx = ep[m * 65 + kq * 4 + 0] + bb.x;
        float fy = ep[m * 65 + kq * 4 + 1] + bb.y;
        float fz = ep[m * 65 + kq * 4 + 2] + bb.z;
        float fw = ep[m * 65 + kq * 4 + 3] + bb.w;
        if (relu) {
            fx = fmaxf(fx, 0.f); fy = fmaxf(fy, 0.f);
            fz = fmaxf(fz, 0.f); fw = fmaxf(fw, 0.f);
        }
        size_t oo = (size_t)(m0 + m) * 512 + n0 + kq * 4;
        if (Cf) {
            *(float4*)(Cf + oo) = make_float4(fx, fy, fz, fw);
        } else {
            __nv_bfloat16 h0 = bhi(fx), h1 = bhi(fy), h2 = bhi(fz), h3 = bhi(fw);
            *(uint2*)(Ch + oo) = make_uint2(pack2(h0, h1), pack2(h2, h3));
            *(uint2*)(Cl + oo) = make_uint2(pack2(blo(fx, h0), blo(fy, h1)),
                                            pack2(blo(fz, h2), blo(fw, h3)));
        }
    }
}

// ===========================================================================
// Prep kernels
// ===========================================================================
__device__ __forceinline__ void wsplit(size_t o, float v) {
    __nv_bfloat16 h = __float2bfloat16_rn(v);
    g_wbf_hi[o] = h;
    g_wbf_lo[o] = __float2bfloat16_rn(v - __bfloat162float(h));
}
__global__ __launch_bounds__(256) void k_prep_qkv(const float* __restrict__ Wq,
    const float* __restrict__ Wk, const float* __restrict__ Wv)
{
    int z = blockIdx.y, which = z >> 3, h = z & 7;
    const float* W = (which == 0 ? Wq : (which == 1 ? Wk : Wv)) + (size_t)h * 32768;
    int i = blockIdx.x * 256 + threadIdx.x;
    int dk = i >> 9, dd = i & 511;
    wsplit((size_t)WOFF_QKV + (size_t)z * 32768 + i, W[dd * 64 + dk]);
}
__global__ __launch_bounds__(256) void k_prep_wo(const float* __restrict__ Wo)
{
    int i = blockIdx.x * 256 + threadIdx.x;
    int dd = i >> 9, hdk = i & 511;
    wsplit((size_t)WOFF_WO + i, Wo[hdk * 512 + dd]);
}
__global__ __launch_bounds__(256) void k_prep_ff(const float* __restrict__ w1,
                                                 const float* __restrict__ w2)
{
    int i = blockIdx.x * 256 + threadIdx.x;
    float v = (i < 262144) ? w1[i] : w2[i - 262144];
    wsplit((size_t)WOFF_FF1 + i, v);
}
__global__ __launch_bounds__(256) void k_prep_x(const float* __restrict__ x)
{
    size_t i = (size_t)blockIdx.x * 256 + threadIdx.x;
    float v = x[i];
    __nv_bfloat16 h = __float2bfloat16_rn(v);
    g_xh[i] = h;
    g_xl[i] = __float2bfloat16_rn(v - __bfloat162float(h));
}

// ===========================================================================
// BatchNorm (deterministic two-stage)
//   mode 0: t = 2*proj(slot0)      mode 1: t = 2*(h(hi+lo) + ff2(slot1))
// ===========================================================================
__global__ __launch_bounds__(256) void k_bnstats(int mode)
{
    int c = blockIdx.x * 256 + threadIdx.x;
    int chunk = blockIdx.y;
    int r0 = chunk * 128;
    float s = 0.f, q = 0.f;
    for (int r = r0; r < r0 + 128; r++) {
        size_t i = (size_t)r * 512 + c;
        float t;
        if (mode == 0) t = 2.f * g_arena[i];
        else t = 2.f * (__bfloat162float(g_hh[i]) + __bfloat162float(g_hl[i])
                        + g_arena[SLOT + i]);
        s += t; q += t * t;
    }
    g_psum[chunk * 512 + c] = s;
    g_psq[chunk * 512 + c]  = q;
}

__global__ __launch_bounds__(512) void k_bnfinal(const float* __restrict__ w,
                                                 const float* __restrict__ bias)
{
    int c = threadIdx.x;
    float s = 0.f, q = 0.f;
    for (int i = 0; i < 256; i++) { s += g_psum[i * 512 + c]; q += g_psq[i * 512 + c]; }
    float m   = s * (1.f / 32768.f);
    float var = q * (1.f / 32768.f) - m * m;
    float inv = rsqrtf(var + 1e-5f);
    float g   = inv * w[c];
    g_gamma[c] = g;
    g_beta[c]  = bias[c] - m * g;
}

// BN1 apply: y = gamma*(2*proj)+beta -> h as bf16 hi/lo
__global__ __launch_bounds__(256) void k_bnapply1()
{
    size_t i = ((size_t)blockIdx.x * 256 + threadIdx.x) * 4;
    int c = (int)(i & 511);
    float4 a = *(const float4*)(g_arena + i);
    float4 g = *(const float4*)&g_gamma[c];
    float4 bt = *(const float4*)&g_beta[c];
    float yx = 2.f * a.x * g.x + bt.x;
    float yy = 2.f * a.y * g.y + bt.y;
    float yz = 2.f * a.z * g.z + bt.z;
    float yw = 2.f * a.w * g.w + bt.w;
    __nv_bfloat16 h0 = bhi(yx), h1 = bhi(yy), h2 = bhi(yz), h3 = bhi(yw);
    *(uint2*)(g_hh + i) = make_uint2(pack2(h0, h1), pack2(h2, h3));
    *(uint2*)(g_hl + i) = make_uint2(pack2(blo(yx, h0), blo(yy, h1)),
                                     pack2(blo(yz, h2), blo(yw, h3)));
}

// BN2 apply: y = gamma*(2*(h+ff2))+beta -> out fp32
__global__ __launch_bounds__(256) void k_bnapply2(float* __restrict__ out)
{
    size_t i = ((size_t)blockIdx.x * 256 + threadIdx.x) * 4;
    int c = (int)(i & 511);
    float4 f = *(const float4*)(g_arena + SLOT + i);
    uint2 hv = *(const uint2*)(g_hh + i);
    uint2 lv = *(const uint2*)(g_hl + i);
    const __nv_bfloat16* hp = (const __nv_bfloat16*)&hv;
    const __nv_bfloat16* lp = (const __nv_bfloat16*)&lv;
    float hx = __bfloat162float(hp[0]) + __bfloat162float(lp[0]);
    float hy = __bfloat162float(hp[1]) + __bfloat162float(lp[1]);
    float hz = __bfloat162float(hp[2]) + __bfloat162float(lp[2]);
    float hw = __bfloat162float(hp[3]) + __bfloat162float(lp[3]);
    float4 g = *(const float4*)&g_gamma[c];
    float4 bt = *(const float4*)&g_beta[c];
    float4 y;
    y.x = 2.f * (hx + f.x) * g.x + bt.x;
    y.y = 2.f * (hy + f.y) * g.y + bt.y;
    y.z = 2.f * (hz + f.z) * g.z + bt.z;
    y.w = 2.f * (hw + f.w) * g.w + bt.w;
    *(float4*)(out + i) = y;
}

// ===========================================================================
// Pipeline
// ===========================================================================
extern "C" void kernel_launch(void* const* d_in, const int* in_sizes, int n_in,
                              void* d_out, int out_size)
{
    const float* x    = (const float*)d_in[0];
    const float* Wq   = (const float*)d_in[1];
    const float* Wk   = (const float*)d_in[2];
    const float* Wv   = (const float*)d_in[3];
    const float* Wo   = (const float*)d_in[4];
    const float* n1w  = (const float*)d_in[5];
    const float* n1b  = (const float*)d_in[6];
    const float* n2w  = (const float*)d_in[7];
    const float* n2b  = (const float*)d_in[8];
    const float* ffw1 = (const float*)d_in[9];
    const float* ffb1 = (const float*)d_in[10];
    const float* ffw2 = (const float*)d_in[11];
    const float* ffb2 = (const float*)d_in[12];

    cudaFuncSetAttribute(k_mm_qkv3, cudaFuncAttributeMaxDynamicSharedMemorySize, QKV_SMEM);
    cudaFuncSetAttribute(k_attn_mma, cudaFuncAttributeMaxDynamicSharedMemorySize, ATTN_SMEM);

    // 0. prep
    k_prep_qkv<<<dim3(128, 24), 256>>>(Wq, Wk, Wv);
    k_prep_wo<<<1024, 256>>>(Wo);
    k_prep_ff<<<2048, 256>>>(ffw1, ffw2);
    k_prep_x<<<65536, 256>>>(x);

    // 1. fused QKV -> bf16 Q/K/Vt
    k_mm_qkv3<<<dim3(256, 8), 256, QKV_SMEM>>>();

    // 2. flash attention -> heads bf16 hi/lo
    k_attn_mma<<<dim3(4, 64, 8), 256, ATTN_SMEM>>>();

    // 3. output projection -> proj fp32 (slot0)
    k_mm_bf<<<dim3(256, 8), 256>>>(0, nullptr);

    // 4. BN1 -> h bf16 hi/lo
    k_bnstats<<<dim3(2, 256), 256>>>(0);
    k_bnfinal<<<1, 512>>>(n1w, n1b);
    k_bnapply1<<<16384, 256>>>();

    // 5. FFN: ff1 bf16 hi/lo, ff2 fp32 (slot1)
    k_mm_bf<<<dim3(256, 8), 256>>>(1, ffb1);
    k_mm_bf<<<dim3(256, 8), 256>>>(2, ffb2);

    // 6. BN2 -> d_out
    k_bnstats<<<dim3(2, 256), 256>>>(1);
    k_bnfinal<<<1, 512>>>(n2w, n2b);
    k_bnapply2<<<16384, 256>>>((float*)d_out);
}